// round 9
// baseline (speedup 1.0000x reference)
#include <cuda_runtime.h>
#include <cuda_fp16.h>
#include <math.h>
#include <float.h>

#define NTR   20000
#define NTE   10000
#define NB    1024
#define NBINS 15
#define NMC   10000
#define NPTS  150000
#define NCLS  10

#define NC1D   16
#define NCELLS 256
#define INVCW  1.6f            // 1/0.625 over [-5,5]

#define GRID  1036             // 148 SMs x 7 blocks
#define BLK   128
#define NWARP (BLK / 32)
#define SPAN  (GRID * BLK)

#define DCH   256              // data points per chunk (padded)
#define TRC   79               // ceil(20000/256)
#define TEC   40               // ceil(10000/256)
#define BAC   4                // 1024/256
#define NCHK  (TRC + TEC + BAC)   // 123
#define NTRP  (TRC * DCH)      // 20224
#define NTEP  (TEC * DCH)      // 10240
#define QT    128              // queries per tile (= BLK)
#define MAXG32 ((NPTS + 31) / 32)
#define CUT2  4.2f             // gap^2 cutoff

#define NSH   (4 * NCELLS + 2 * NBINS + 1)   // 1055

// c = log2(e) / (2*BW^2)
#define CC   8.014972449383130f
#define CC2  16.029944898766260f
#define KDE_NORM_D 0.5654866776461628

// ---------------- static device scratch ----------------
__device__ __align__(16) float g_u0[NTRP], g_v0[NTRP], g_f0[NTRP];
__device__ __align__(16) float g_u1[NTEP], g_v1[NTEP], g_f1[NTEP];
__device__ __align__(16) float g_u2[NB],   g_v2[NB],   g_f2[NB];
__device__ float4 g_tq[NPTS];        // unsorted survivors (x, y, 0, bin-bits)
__device__ float4 g_q[NPTS];         // sorted survivors  (x, y, e, bin-bits)
__device__ float  g_s0[NPTS], g_s1[NPTS], g_s2[NPTS];
__device__ int    g_M, g_cnt;
__device__ int    g_ccnt[4 * NCELLS];
__device__ int    g_cur[4 * NCELLS];
__device__ int    g_htr[NBINS], g_hte[NBINS];
__device__ double g_integral[NBINS];
__device__ float4 g_cbb[NCHK];        // chunk bboxes
__device__ float4 g_sbb[NCHK * 8];    // 32-pt data-subgroup bboxes
__device__ float4 g_wbb[MAXG32];      // 32-query-group bboxes
__device__ int    g_ticket;
__device__ __align__(128) int g_bar_cnt;
__device__ __align__(128) int g_bar_gen;

union ShU {
    int sh[NSH];                                              // phase A
    struct { int h[4 * NCELLS]; int hbase[4 * NCELLS]; } sc;  // phase C (8KB)
    struct { ulonglong2 su[DCH/4], sv[DCH/4], sf[DCH/4];
             float4 sbb[8]; int item; } kd;                   // phase E (~3.2KB)
    double bins[NBINS];                                       // phase F
};

__device__ __forceinline__ int mort4(int cx, int cy) {
    int m = (cx & 1) | ((cy & 1) << 1);
    m |= ((cx & 2) << 1) | ((cy & 2) << 2);
    m |= ((cx & 4) << 2) | ((cy & 4) << 3);
    m |= ((cx & 8) << 3) | ((cy & 8) << 4);
    return m;
}
__device__ __forceinline__ int cellof(float x, float y) {
    int cx = (int)((x + 5.0f) * INVCW);
    int cy = (int)((y + 5.0f) * INVCW);
    cx = min(NC1D - 1, max(0, cx));
    cy = min(NC1D - 1, max(0, cy));
    return mort4(cx, cy);
}
// bin index matching (p > b/15 && p <= (b+1)/15); -1 if none
__device__ __forceinline__ int binof(float p) {
    int b = (int)ceilf(p * 15.0f) - 1;
    b = min(14, max(0, b));
    if (!(p > (float)b * (1.0f / 15.0f))) b -= 1;
    else if (p > (float)(b + 1) * (1.0f / 15.0f)) b += 1;
    if (b < 0 || b > 14) return -1;
    if (!(p > (float)b * (1.0f / 15.0f)) || !(p <= (float)(b + 1) * (1.0f / 15.0f))) return -1;
    return b;
}
__device__ __forceinline__ unsigned long long pk2(float lo, float hi) {
    unsigned long long r;
    asm("mov.b64 %0, {%1, %2};" : "=l"(r) : "f"(lo), "f"(hi));
    return r;
}
// packed unit: exp2 of (u*qx + v*qy + f + e) for 2 points -> half2
__device__ __forceinline__ __half2 eunit(unsigned long long uu, unsigned long long vv,
                                         unsigned long long ff,
                                         unsigned long long qx2, unsigned long long qy2,
                                         unsigned long long e2) {
    unsigned long long t;
    asm("add.rn.f32x2 %0, %1, %2;"      : "=l"(t) : "l"(ff), "l"(e2));
    asm("fma.rn.f32x2 %0, %1, %2, %3;"  : "=l"(t) : "l"(vv), "l"(qy2), "l"(t));
    asm("fma.rn.f32x2 %0, %1, %2, %3;"  : "=l"(t) : "l"(uu), "l"(qx2), "l"(t));
    float lo, hi;
    asm("mov.b64 {%0, %1}, %2;" : "=f"(lo), "=f"(hi) : "l"(t));
    return h2exp2(__floats2half2_rn(lo, hi));
}

// fence-cumulative grid barrier (all GRID blocks resident by construction)
__device__ __forceinline__ void gridbar() {
    __syncthreads();
    if (threadIdx.x == 0) {
        __threadfence();
        int gen = atomicAdd(&g_bar_gen, 0);
        if (atomicAdd(&g_bar_cnt, 1) == GRID - 1) {
            atomicExch(&g_bar_cnt, 0);
            __threadfence();
            atomicExch(&g_bar_gen, gen + 1);
        } else {
            while (*(volatile int*)&g_bar_gen == gen) { __nanosleep(64); }
        }
        __threadfence();
    }
    __syncthreads();
}

__global__ void __launch_bounds__(BLK, 7) k_all(
    const float* __restrict__ trx, const float* __restrict__ tex,
    const float* __restrict__ bx, const int* __restrict__ by,
    const int* __restrict__ bp, const float* __restrict__ trp,
    const float* __restrict__ tep, const float* __restrict__ mc,
    const float* __restrict__ W, const float* __restrict__ bvec,
    float* __restrict__ out)
{
    __shared__ ShU u;
    const int tid = threadIdx.x;
    const int gid = blockIdx.x * BLK + tid;

    // ---------- phase 0: zero globals + init SoA padding ----------
    if (gid < 4 * NCELLS) g_ccnt[gid] = 0;
    else if (gid < 4 * NCELLS + NBINS)       g_htr[gid - 4 * NCELLS] = 0;
    else if (gid < 4 * NCELLS + 2 * NBINS)   g_hte[gid - 4 * NCELLS - NBINS] = 0;
    else if (gid < 4 * NCELLS + 3 * NBINS)   g_integral[gid - 4 * NCELLS - 2 * NBINS] = 0.0;
    else if (gid == 4 * NCELLS + 3 * NBINS)  { g_M = 0; g_cnt = 0; g_ticket = 0; }
    {
        int k = gid - 2048;
        if (k >= 0 && k < NTRP - NTR) { g_u0[NTR + k] = 0.f; g_v0[NTR + k] = 0.f; g_f0[NTR + k] = -1e30f; }
        int k2 = gid - 4096;
        if (k2 >= 0 && k2 < NTEP - NTE) { g_u1[NTE + k2] = 0.f; g_v1[NTE + k2] = 0.f; g_f1[NTE + k2] = -1e30f; }
    }
    gridbar();

    // ---------- phase A: cell counts + hists + cnt + filter/compact ----------
    for (int s = tid; s < NSH; s += BLK) u.sh[s] = 0;
    __syncthreads();
    for (int i0 = 0; i0 < NPTS; i0 += SPAN) {
        int i = i0 + gid;
        if (i < NTR) {
            atomicAdd(&u.sh[NCELLS + cellof(trx[2 * i], trx[2 * i + 1])], 1);
            int b = binof(trp[i]);
            if (b >= 0) atomicAdd(&u.sh[4 * NCELLS + b], 1);
        }
        if (i < NTE) {
            atomicAdd(&u.sh[2 * NCELLS + cellof(tex[2 * i], tex[2 * i + 1])], 1);
            int b = binof(tep[i]);
            if (b >= 0) atomicAdd(&u.sh[4 * NCELLS + NBINS + b], 1);
        }
        if (i < NB) {
            atomicAdd(&u.sh[3 * NCELLS + cellof(bx[2 * i], bx[2 * i + 1])], 1);
            if (by[i] == bp[i]) atomicAdd(&u.sh[4 * NCELLS + 2 * NBINS], 1);
        }
        bool pass = false;
        float qx = 0.f, qy = 0.f;
        int bin = 0;
        if (i < NPTS) {
            bin = i / NMC;
            qx = mc[2 * i]; qy = mc[2 * i + 1];
            float l[NCLS], lmax = -FLT_MAX;
            #pragma unroll
            for (int c = 0; c < NCLS; c++) {
                float v = fmaf(qx, __ldg(&W[c]), fmaf(qy, __ldg(&W[NCLS + c]), __ldg(&bvec[c])));
                l[c] = v; lmax = fmaxf(lmax, v);
            }
            float s = 0.f;
            #pragma unroll
            for (int c = 0; c < NCLS; c++) s += __expf(l[c] - lmax);
            float hs = 1.0f / s;
            float lo = (float)bin * (1.0f / 15.0f);
            float hi = (float)(bin + 1) * (1.0f / 15.0f);
            pass = (hs >= lo && hs <= hi);
        }
        unsigned mask = __ballot_sync(0xffffffffu, pass);
        if (pass) {
            int lane = tid & 31;
            int leader = __ffs(mask) - 1;
            int rank = __popc(mask & ((1u << lane) - 1));
            int base = 0;
            if (lane == leader) base = atomicAdd(&g_M, __popc(mask));
            base = __shfl_sync(mask, base, leader);
            g_tq[base + rank] = make_float4(qx, qy, 0.f, __int_as_float(bin));
            atomicAdd(&u.sh[cellof(qx, qy)], 1);
        }
    }
    __syncthreads();
    for (int s = tid; s < NSH; s += BLK) {
        int v = u.sh[s];
        if (!v) continue;
        if (s < 4 * NCELLS)                    atomicAdd(&g_ccnt[s], v);
        else if (s < 4 * NCELLS + NBINS)       atomicAdd(&g_htr[s - 4 * NCELLS], v);
        else if (s < 4 * NCELLS + 2 * NBINS)   atomicAdd(&g_hte[s - 4 * NCELLS - NBINS], v);
        else                                   atomicAdd(&g_cnt, v);
    }
    gridbar();

    // ---------- phase B: exclusive scans (block 0, 4 warps, 8 cells/lane) ----------
    if (blockIdx.x == 0 && tid < 128) {
        int a = tid >> 5, lane = tid & 31;
        int base = a * NCELLS + lane * 8;
        int v[8], pre[8], run = 0;
        #pragma unroll
        for (int k = 0; k < 8; k++) { v[k] = g_ccnt[base + k]; pre[k] = run; run += v[k]; }
        int inc = run;
        #pragma unroll
        for (int o = 1; o < 32; o <<= 1) {
            int n = __shfl_up_sync(0xffffffffu, inc, o);
            if (lane >= o) inc += n;
        }
        int excl = inc - run;
        #pragma unroll
        for (int k = 0; k < 8; k++) g_cur[base + k] = excl + pre[k];
    }
    gridbar();

    const int M = g_M;

    // ---------- phase C: block-aggregated scatter to SoA ----------
    for (int i0 = 0; i0 < NPTS; i0 += SPAN) {
        for (int s = tid; s < 4 * NCELLS; s += BLK) u.sc.h[s] = 0;
        __syncthreads();
        int i = i0 + gid;
        float qx = 0.f, qy = 0.f, qw = 0.f; int qc = -1, qr = 0;
        if (i < M) {
            float4 q = g_tq[i];
            qx = q.x; qy = q.y; qw = q.w;
            qc = cellof(qx, qy);
            qr = atomicAdd(&u.sc.h[qc], 1);
        }
        float tx = 0.f, ty = 0.f; int tc = -1, trk = 0;
        if (i < NTR) {
            tx = trx[2 * i]; ty = trx[2 * i + 1];
            tc = cellof(tx, ty);
            trk = atomicAdd(&u.sc.h[NCELLS + tc], 1);
        }
        float ex = 0.f, ey = 0.f; int ecl = -1, erk = 0;
        if (i < NTE) {
            ex = tex[2 * i]; ey = tex[2 * i + 1];
            ecl = cellof(ex, ey);
            erk = atomicAdd(&u.sc.h[2 * NCELLS + ecl], 1);
        }
        float bxx = 0.f, byy = 0.f; int bcl = -1, brk = 0; bool bok = false;
        if (i < NB) {
            bxx = bx[2 * i]; byy = bx[2 * i + 1];
            bok = (by[i] == bp[i]);
            bcl = cellof(bxx, byy);
            brk = atomicAdd(&u.sc.h[3 * NCELLS + bcl], 1);
        }
        __syncthreads();
        for (int s = tid; s < 4 * NCELLS; s += BLK) {
            int c = u.sc.h[s];
            if (c) u.sc.hbase[s] = atomicAdd(&g_cur[s], c);
        }
        __syncthreads();
        if (qc >= 0) {
            int pos = u.sc.hbase[qc] + qr;
            g_q[pos] = make_float4(qx, qy, -CC * (qx * qx + qy * qy), qw);
            g_s0[pos] = 0.f; g_s1[pos] = 0.f; g_s2[pos] = 0.f;
        }
        if (tc >= 0) {
            int pos = u.sc.hbase[NCELLS + tc] + trk;
            g_u0[pos] = CC2 * tx; g_v0[pos] = CC2 * ty; g_f0[pos] = -CC * (tx * tx + ty * ty);
        }
        if (ecl >= 0) {
            int pos = u.sc.hbase[2 * NCELLS + ecl] + erk;
            g_u1[pos] = CC2 * ex; g_v1[pos] = CC2 * ey; g_f1[pos] = -CC * (ex * ex + ey * ey);
        }
        if (bcl >= 0) {
            int pos = u.sc.hbase[3 * NCELLS + bcl] + brk;
            g_u2[pos] = CC2 * bxx; g_v2[pos] = CC2 * byy;
            g_f2[pos] = bok ? -CC * (bxx * bxx + byy * byy) : -1e30f;
        }
        __syncthreads();
    }
    gridbar();

    // ---------- phase D: bboxes (warp/item): chunks, 32-pt data subgroups, 32-query groups ----------
    const int ngroups = (M + 31) >> 5;
    {
        int gw = blockIdx.x * NWARP + (tid >> 5);
        int lane = tid & 31;
        int nit = NCHK * 9 + ngroups;
        for (int it = gw; it < nit; it += GRID * NWARP) {
            float mnx = FLT_MAX, mny = FLT_MAX, mxx = -FLT_MAX, mxy = -FLT_MAX;
            if (it < NCHK * 9) {
                int c, sg;
                if (it < NCHK) { c = it; sg = -1; }
                else { int idx = it - NCHK; c = idx >> 3; sg = idx & 7; }
                const float *pu, *pv; int start, len;
                if (c < TRC)            { pu = g_u0; pv = g_v0; start = c * DCH;        len = min(DCH, NTR - start); }
                else if (c < TRC + TEC) { pu = g_u1; pv = g_v1; start = (c - TRC) * DCH; len = min(DCH, NTE - start); }
                else                    { pu = g_u2; pv = g_v2; start = (c - TRC - TEC) * DCH; len = DCH; }
                if (sg >= 0) { start += sg * 32; len = min(32, len - sg * 32); }
                for (int j = lane; j < len; j += 32) {
                    float x = pu[start + j] * (1.0f / CC2), y = pv[start + j] * (1.0f / CC2);
                    mnx = fminf(mnx, x); mxx = fmaxf(mxx, x);
                    mny = fminf(mny, y); mxy = fmaxf(mxy, y);
                }
            } else {
                int g = it - NCHK * 9;
                int start = g * 32;
                int len = min(32, M - start);
                if (lane < len) {
                    float4 q = g_q[start + lane];
                    mnx = mxx = q.x; mny = mxy = q.y;
                }
            }
            #pragma unroll
            for (int o = 16; o; o >>= 1) {
                mnx = fminf(mnx, __shfl_xor_sync(0xffffffffu, mnx, o));
                mny = fminf(mny, __shfl_xor_sync(0xffffffffu, mny, o));
                mxx = fmaxf(mxx, __shfl_xor_sync(0xffffffffu, mxx, o));
                mxy = fmaxf(mxy, __shfl_xor_sync(0xffffffffu, mxy, o));
            }
            if (lane == 0) {
                float4 bb = make_float4(mnx, mny, mxx, mxy);
                if (it < NCHK) g_cbb[it] = bb;
                else if (it < NCHK * 9) g_sbb[it - NCHK] = bb;
                else g_wbb[it - NCHK * 9] = bb;
            }
        }
    }
    gridbar();

    // ---------- phase E: packed-f32x2 / f16x2-exp KDE with subgroup cull ----------
    {
        const int tiles = (M + QT - 1) / QT;
        const int nitems = tiles * NCHK;
        for (;;) {
            if (tid == 0) u.kd.item = atomicAdd(&g_ticket, 1);
            __syncthreads();                 // publish item
            int item = u.kd.item;
            if (item >= nitems) break;
            int tile = item / NCHK;
            int c = item - tile * NCHK;

            float4 cb = __ldg(&g_cbb[c]);
            int grp = (tile << 2) + (tid >> 5);
            float4 wb = make_float4(0.f, 0.f, 0.f, 0.f);
            int pass_w = 0;
            if (grp < ngroups) {
                wb = __ldg(&g_wbb[grp]);
                float ddx = fmaxf(0.f, fmaxf(cb.x - wb.z, wb.x - cb.z));
                float ddy = fmaxf(0.f, fmaxf(cb.y - wb.w, wb.y - cb.w));
                pass_w = (ddx * ddx + ddy * ddy) <= CUT2;
            }
            if (__syncthreads_or(pass_w) == 0) continue;   // block-uniform skip

            const float *pu, *pv, *pf; float* dst; int start;
            if (c < TRC)            { pu = g_u0; pv = g_v0; pf = g_f0; dst = g_s0; start = c * DCH; }
            else if (c < TRC + TEC) { pu = g_u1; pv = g_v1; pf = g_f1; dst = g_s1; start = (c - TRC) * DCH; }
            else                    { pu = g_u2; pv = g_v2; pf = g_f2; dst = g_s2; start = (c - TRC - TEC) * DCH; }

            for (int k = tid; k < 192; k += BLK) {
                int a = k >> 6, kk = k & 63;
                const float* base = (a == 0) ? pu : (a == 1) ? pv : pf;
                const ulonglong2* s = reinterpret_cast<const ulonglong2*>(base + start);
                ulonglong2* d = (a == 0) ? u.kd.su : (a == 1) ? u.kd.sv : u.kd.sf;
                d[kk] = s[kk];
            }
            if (tid < 8) u.kd.sbb[tid] = g_sbb[(c << 3) + tid];
            __syncthreads();

            if (pass_w) {
                int p = (tile << 7) + tid;
                float4 q = __ldg(&g_q[p < M ? p : 0]);
                unsigned long long qx2 = pk2(q.x, q.x);
                unsigned long long qy2 = pk2(q.y, q.y);
                unsigned long long e2  = pk2(q.z, q.z);
                float ssum = 0.f;
                #pragma unroll 1
                for (int sg = 0; sg < 8; sg++) {        // 8 subgroups of 32 points
                    float4 sb = u.kd.sbb[sg];
                    float gx = fmaxf(0.f, fmaxf(sb.x - wb.z, wb.x - sb.z));
                    float gy = fmaxf(0.f, fmaxf(sb.y - wb.w, wb.y - sb.w));
                    if (gx * gx + gy * gy > CUT2) continue;   // warp-uniform skip
                    int base = sg << 3;
                    __half2 h0 = __floats2half2_rn(0.f, 0.f);
                    __half2 h1 = h0, h2 = h0, h3 = h0;
                    #pragma unroll
                    for (int j = 0; j < 8; j += 2) {
                        ulonglong2 U0 = u.kd.su[base + j],     V0 = u.kd.sv[base + j],     F0 = u.kd.sf[base + j];
                        ulonglong2 U1 = u.kd.su[base + j + 1], V1 = u.kd.sv[base + j + 1], F1 = u.kd.sf[base + j + 1];
                        h0 = __hadd2(h0, eunit(U0.x, V0.x, F0.x, qx2, qy2, e2));
                        h1 = __hadd2(h1, eunit(U0.y, V0.y, F0.y, qx2, qy2, e2));
                        h2 = __hadd2(h2, eunit(U1.x, V1.x, F1.x, qx2, qy2, e2));
                        h3 = __hadd2(h3, eunit(U1.y, V1.y, F1.y, qx2, qy2, e2));
                    }
                    float2 f0 = __half22float2(__hadd2(__hadd2(h0, h1), __hadd2(h2, h3)));
                    ssum += f0.x + f0.y;
                }
                if (p < M && ssum != 0.f) atomicAdd(&dst[p], ssum);
            }
        }
    }
    gridbar();

    // ---------- phase F: per-point finalize + per-bin integral ----------
    {
        for (int s = tid; s < NBINS; s += BLK) u.bins[s] = 0.0;
        __syncthreads();
        float cntf = (float)g_cnt;
        float p_y = cntf / (float)NB;
        for (int p = gid; p < M; p += SPAN) {
            int bin = __float_as_int(g_q[p].w);
            float ktr = g_s0[p] * (float)(1.0 / (NTR * KDE_NORM_D));
            float kte = g_s1[p] * (float)(1.0 / (NTE * KDE_NORM_D));
            float kw  = g_s2[p] / (fmaxf(cntf, 1.0f) * (float)KDE_NORM_D);
            float p_hs = fminf(fmaxf(kw * p_y / (ktr + 1e-8f), 0.0f), 1.0f);
            float ter = (float)g_hte[bin] * (1.0f / NTE);
            float trr = (float)g_htr[bin] * (1.0f / NTR);
            float d_t = (ter > 0.f) ? kte / ter : 0.f;
            float d_s = (trr > 0.f) ? ktr / trr : 0.f;
            atomicAdd(&u.bins[bin], (double)(p_hs * (d_t - d_s)));
        }
        __syncthreads();
        for (int s = tid; s < NBINS; s += BLK) {
            double v = u.bins[s];
            if (v != 0.0) atomicAdd(&g_integral[s], v);
        }
    }
    gridbar();

    // ---------- phase G: final scalar ----------
    if (blockIdx.x == 0 && tid == 0) {
        double ec = 0.0;
        for (int b = 0; b < NBINS; b++) {
            float ter = (float)g_hte[b] * (1.0f / NTE);
            if (ter > 0.f) {
                double integ = g_integral[b] / (double)NMC * 100.0;   // VOLUME
                ec += (double)ter * fabs(integ);
            }
        }
        out[0] = (float)ec;
    }
}

// ---------------- launch ----------------
extern "C" void kernel_launch(void* const* d_in, const int* in_sizes, int n_in,
                              void* d_out, int out_size) {
    const float *bx = nullptr, *trp = nullptr, *tep = nullptr;
    const float *trx = nullptr, *tex = nullptr, *W = nullptr, *bv = nullptr, *mc = nullptr;
    const int *by = nullptr, *bp = nullptr;
    for (int i = 0; i < n_in; i++) {
        switch (in_sizes[i]) {
            case 2048:   bx = (const float*)d_in[i]; break;
            case 1024:   if (!by) by = (const int*)d_in[i]; else bp = (const int*)d_in[i]; break;
            case 20000:  if (!trp) trp = (const float*)d_in[i]; else tex = (const float*)d_in[i]; break;
            case 10000:  tep = (const float*)d_in[i]; break;
            case 40000:  trx = (const float*)d_in[i]; break;
            case 20:     W = (const float*)d_in[i]; break;
            case 10:     bv = (const float*)d_in[i]; break;
            case 300000: mc = (const float*)d_in[i]; break;
            default: break;
        }
    }
    k_all<<<GRID, BLK>>>(trx, tex, bx, by, bp, trp, tep, mc, W, bv, (float*)d_out);
}

// round 10
// speedup vs baseline: 1.0154x; 1.0154x over previous
#include <cuda_runtime.h>
#include <cuda_fp16.h>
#include <math.h>
#include <float.h>

#define NTR   20000
#define NTE   10000
#define NB    1024
#define NBINS 15
#define NMC   10000
#define NPTS  150000
#define NCLS  10

#define NC1D   16
#define NCELLS 256
#define INVCW  1.6f            // 1/0.625 over [-5,5]

#define GRID  1036             // 148 SMs x 7 blocks (k_pre, all-resident)
#define BLK   128
#define NWARP (BLK / 32)
#define SPAN  (GRID * BLK)
#define KGRID 4096             // k_kde grid (wave-scheduled)

#define DCH   256              // data points per chunk (padded)
#define TRC   79               // ceil(20000/256)
#define TEC   40               // ceil(10000/256)
#define BAC   4                // 1024/256
#define NCHK  (TRC + TEC + BAC)   // 123
#define NTRP  (TRC * DCH)      // 20224
#define NTEP  (TEC * DCH)      // 10240
#define QT    128              // queries per tile
#define MAXG32 ((NPTS + 31) / 32)
#define CUT2  4.2f             // gap^2 cutoff

#define NSH   (4 * NCELLS + 2 * NBINS + 1)   // 1055

// c = log2(e) / (2*BW^2)
#define CC   8.014972449383130f
#define CC2  16.029944898766260f
#define KDE_NORM_D 0.5654866776461628

// ---------------- static device scratch ----------------
__device__ __align__(16) float g_u0[NTRP], g_v0[NTRP], g_f0[NTRP];
__device__ __align__(16) float g_u1[NTEP], g_v1[NTEP], g_f1[NTEP];
__device__ __align__(16) float g_u2[NB],   g_v2[NB],   g_f2[NB];
__device__ float4 g_tq[NPTS];
__device__ float4 g_q[NPTS];
__device__ float  g_s0[NPTS], g_s1[NPTS], g_s2[NPTS];
__device__ int    g_M, g_cnt;
__device__ int    g_ccnt[4 * NCELLS];
__device__ int    g_cur[4 * NCELLS];
__device__ int    g_htr[NBINS], g_hte[NBINS];
__device__ double g_integral[NBINS];
__device__ float4 g_cbb[NCHK];
__device__ float4 g_sbb[NCHK * 8];
__device__ float4 g_wbb[MAXG32];
__device__ __align__(128) int g_bar_cnt;
__device__ __align__(128) int g_bar_gen;

union ShU {
    int sh[NSH];
    struct { int h[4 * NCELLS]; int hbase[4 * NCELLS]; } sc;
};

__device__ __forceinline__ int mort4(int cx, int cy) {
    int m = (cx & 1) | ((cy & 1) << 1);
    m |= ((cx & 2) << 1) | ((cy & 2) << 2);
    m |= ((cx & 4) << 2) | ((cy & 4) << 3);
    m |= ((cx & 8) << 3) | ((cy & 8) << 4);
    return m;
}
__device__ __forceinline__ int cellof(float x, float y) {
    int cx = (int)((x + 5.0f) * INVCW);
    int cy = (int)((y + 5.0f) * INVCW);
    cx = min(NC1D - 1, max(0, cx));
    cy = min(NC1D - 1, max(0, cy));
    return mort4(cx, cy);
}
__device__ __forceinline__ int binof(float p) {
    int b = (int)ceilf(p * 15.0f) - 1;
    b = min(14, max(0, b));
    if (!(p > (float)b * (1.0f / 15.0f))) b -= 1;
    else if (p > (float)(b + 1) * (1.0f / 15.0f)) b += 1;
    if (b < 0 || b > 14) return -1;
    if (!(p > (float)b * (1.0f / 15.0f)) || !(p <= (float)(b + 1) * (1.0f / 15.0f))) return -1;
    return b;
}
__device__ __forceinline__ unsigned long long pk2(float lo, float hi) {
    unsigned long long r;
    asm("mov.b64 %0, {%1, %2};" : "=l"(r) : "f"(lo), "f"(hi));
    return r;
}
__device__ __forceinline__ __half2 eunit(unsigned long long uu, unsigned long long vv,
                                         unsigned long long ff,
                                         unsigned long long qx2, unsigned long long qy2,
                                         unsigned long long e2) {
    unsigned long long t;
    asm("add.rn.f32x2 %0, %1, %2;"      : "=l"(t) : "l"(ff), "l"(e2));
    asm("fma.rn.f32x2 %0, %1, %2, %3;"  : "=l"(t) : "l"(vv), "l"(qy2), "l"(t));
    asm("fma.rn.f32x2 %0, %1, %2, %3;"  : "=l"(t) : "l"(uu), "l"(qx2), "l"(t));
    float lo, hi;
    asm("mov.b64 {%0, %1}, %2;" : "=f"(lo), "=f"(hi) : "l"(t));
    return h2exp2(__floats2half2_rn(lo, hi));
}

// fence-cumulative grid barrier (k_pre only; all GRID blocks resident)
__device__ __forceinline__ void gridbar() {
    __syncthreads();
    if (threadIdx.x == 0) {
        __threadfence();
        int gen = atomicAdd(&g_bar_gen, 0);
        if (atomicAdd(&g_bar_cnt, 1) == GRID - 1) {
            atomicExch(&g_bar_cnt, 0);
            __threadfence();
            atomicExch(&g_bar_gen, gen + 1);
        } else {
            while (*(volatile int*)&g_bar_gen == gen) { __nanosleep(64); }
        }
        __threadfence();
    }
    __syncthreads();
}

// ============ k_pre: phases 0, A (filter/hist), B (scan), C (scatter), D (bboxes) ============
__global__ void __launch_bounds__(BLK, 7) k_pre(
    const float* __restrict__ trx, const float* __restrict__ tex,
    const float* __restrict__ bx, const int* __restrict__ by,
    const int* __restrict__ bp, const float* __restrict__ trp,
    const float* __restrict__ tep, const float* __restrict__ mc,
    const float* __restrict__ W, const float* __restrict__ bvec)
{
    __shared__ ShU u;
    const int tid = threadIdx.x;
    const int gid = blockIdx.x * BLK + tid;

    // ---------- phase 0 ----------
    if (gid < 4 * NCELLS) g_ccnt[gid] = 0;
    else if (gid < 4 * NCELLS + NBINS)       g_htr[gid - 4 * NCELLS] = 0;
    else if (gid < 4 * NCELLS + 2 * NBINS)   g_hte[gid - 4 * NCELLS - NBINS] = 0;
    else if (gid < 4 * NCELLS + 3 * NBINS)   g_integral[gid - 4 * NCELLS - 2 * NBINS] = 0.0;
    else if (gid == 4 * NCELLS + 3 * NBINS)  { g_M = 0; g_cnt = 0; }
    {
        int k = gid - 2048;
        if (k >= 0 && k < NTRP - NTR) { g_u0[NTR + k] = 0.f; g_v0[NTR + k] = 0.f; g_f0[NTR + k] = -1e30f; }
        int k2 = gid - 4096;
        if (k2 >= 0 && k2 < NTEP - NTE) { g_u1[NTE + k2] = 0.f; g_v1[NTE + k2] = 0.f; g_f1[NTE + k2] = -1e30f; }
    }
    gridbar();

    // ---------- phase A ----------
    for (int s = tid; s < NSH; s += BLK) u.sh[s] = 0;
    __syncthreads();
    for (int i0 = 0; i0 < NPTS; i0 += SPAN) {
        int i = i0 + gid;
        if (i < NTR) {
            atomicAdd(&u.sh[NCELLS + cellof(trx[2 * i], trx[2 * i + 1])], 1);
            int b = binof(trp[i]);
            if (b >= 0) atomicAdd(&u.sh[4 * NCELLS + b], 1);
        }
        if (i < NTE) {
            atomicAdd(&u.sh[2 * NCELLS + cellof(tex[2 * i], tex[2 * i + 1])], 1);
            int b = binof(tep[i]);
            if (b >= 0) atomicAdd(&u.sh[4 * NCELLS + NBINS + b], 1);
        }
        if (i < NB) {
            atomicAdd(&u.sh[3 * NCELLS + cellof(bx[2 * i], bx[2 * i + 1])], 1);
            if (by[i] == bp[i]) atomicAdd(&u.sh[4 * NCELLS + 2 * NBINS], 1);
        }
        bool pass = false;
        float qx = 0.f, qy = 0.f;
        int bin = 0;
        if (i < NPTS) {
            bin = i / NMC;
            qx = mc[2 * i]; qy = mc[2 * i + 1];
            float l[NCLS], lmax = -FLT_MAX;
            #pragma unroll
            for (int c = 0; c < NCLS; c++) {
                float v = fmaf(qx, __ldg(&W[c]), fmaf(qy, __ldg(&W[NCLS + c]), __ldg(&bvec[c])));
                l[c] = v; lmax = fmaxf(lmax, v);
            }
            float s = 0.f;
            #pragma unroll
            for (int c = 0; c < NCLS; c++) s += __expf(l[c] - lmax);
            float hs = 1.0f / s;
            float lo = (float)bin * (1.0f / 15.0f);
            float hi = (float)(bin + 1) * (1.0f / 15.0f);
            pass = (hs >= lo && hs <= hi);
        }
        unsigned mask = __ballot_sync(0xffffffffu, pass);
        if (pass) {
            int lane = tid & 31;
            int leader = __ffs(mask) - 1;
            int rank = __popc(mask & ((1u << lane) - 1));
            int base = 0;
            if (lane == leader) base = atomicAdd(&g_M, __popc(mask));
            base = __shfl_sync(mask, base, leader);
            g_tq[base + rank] = make_float4(qx, qy, 0.f, __int_as_float(bin));
            atomicAdd(&u.sh[cellof(qx, qy)], 1);
        }
    }
    __syncthreads();
    for (int s = tid; s < NSH; s += BLK) {
        int v = u.sh[s];
        if (!v) continue;
        if (s < 4 * NCELLS)                    atomicAdd(&g_ccnt[s], v);
        else if (s < 4 * NCELLS + NBINS)       atomicAdd(&g_htr[s - 4 * NCELLS], v);
        else if (s < 4 * NCELLS + 2 * NBINS)   atomicAdd(&g_hte[s - 4 * NCELLS - NBINS], v);
        else                                   atomicAdd(&g_cnt, v);
    }
    gridbar();

    // ---------- phase B ----------
    if (blockIdx.x == 0 && tid < 128) {
        int a = tid >> 5, lane = tid & 31;
        int base = a * NCELLS + lane * 8;
        int v[8], pre[8], run = 0;
        #pragma unroll
        for (int k = 0; k < 8; k++) { v[k] = g_ccnt[base + k]; pre[k] = run; run += v[k]; }
        int inc = run;
        #pragma unroll
        for (int o = 1; o < 32; o <<= 1) {
            int n = __shfl_up_sync(0xffffffffu, inc, o);
            if (lane >= o) inc += n;
        }
        int excl = inc - run;
        #pragma unroll
        for (int k = 0; k < 8; k++) g_cur[base + k] = excl + pre[k];
    }
    gridbar();

    const int M = g_M;

    // ---------- phase C ----------
    for (int i0 = 0; i0 < NPTS; i0 += SPAN) {
        for (int s = tid; s < 4 * NCELLS; s += BLK) u.sc.h[s] = 0;
        __syncthreads();
        int i = i0 + gid;
        float qx = 0.f, qy = 0.f, qw = 0.f; int qc = -1, qr = 0;
        if (i < M) {
            float4 q = g_tq[i];
            qx = q.x; qy = q.y; qw = q.w;
            qc = cellof(qx, qy);
            qr = atomicAdd(&u.sc.h[qc], 1);
        }
        float tx = 0.f, ty = 0.f; int tc = -1, trk = 0;
        if (i < NTR) {
            tx = trx[2 * i]; ty = trx[2 * i + 1];
            tc = cellof(tx, ty);
            trk = atomicAdd(&u.sc.h[NCELLS + tc], 1);
        }
        float ex = 0.f, ey = 0.f; int ecl = -1, erk = 0;
        if (i < NTE) {
            ex = tex[2 * i]; ey = tex[2 * i + 1];
            ecl = cellof(ex, ey);
            erk = atomicAdd(&u.sc.h[2 * NCELLS + ecl], 1);
        }
        float bxx = 0.f, byy = 0.f; int bcl = -1, brk = 0; bool bok = false;
        if (i < NB) {
            bxx = bx[2 * i]; byy = bx[2 * i + 1];
            bok = (by[i] == bp[i]);
            bcl = cellof(bxx, byy);
            brk = atomicAdd(&u.sc.h[3 * NCELLS + bcl], 1);
        }
        __syncthreads();
        for (int s = tid; s < 4 * NCELLS; s += BLK) {
            int c = u.sc.h[s];
            if (c) u.sc.hbase[s] = atomicAdd(&g_cur[s], c);
        }
        __syncthreads();
        if (qc >= 0) {
            int pos = u.sc.hbase[qc] + qr;
            g_q[pos] = make_float4(qx, qy, -CC * (qx * qx + qy * qy), qw);
            g_s0[pos] = 0.f; g_s1[pos] = 0.f; g_s2[pos] = 0.f;
        }
        if (tc >= 0) {
            int pos = u.sc.hbase[NCELLS + tc] + trk;
            g_u0[pos] = CC2 * tx; g_v0[pos] = CC2 * ty; g_f0[pos] = -CC * (tx * tx + ty * ty);
        }
        if (ecl >= 0) {
            int pos = u.sc.hbase[2 * NCELLS + ecl] + erk;
            g_u1[pos] = CC2 * ex; g_v1[pos] = CC2 * ey; g_f1[pos] = -CC * (ex * ex + ey * ey);
        }
        if (bcl >= 0) {
            int pos = u.sc.hbase[3 * NCELLS + bcl] + brk;
            g_u2[pos] = CC2 * bxx; g_v2[pos] = CC2 * byy;
            g_f2[pos] = bok ? -CC * (bxx * bxx + byy * byy) : -1e30f;
        }
        __syncthreads();
    }
    gridbar();

    // ---------- phase D ----------
    const int ngroups = (M + 31) >> 5;
    {
        int gw = blockIdx.x * NWARP + (tid >> 5);
        int lane = tid & 31;
        int nit = NCHK * 9 + ngroups;
        for (int it = gw; it < nit; it += GRID * NWARP) {
            float mnx = FLT_MAX, mny = FLT_MAX, mxx = -FLT_MAX, mxy = -FLT_MAX;
            if (it < NCHK * 9) {
                int c, sg;
                if (it < NCHK) { c = it; sg = -1; }
                else { int idx = it - NCHK; c = idx >> 3; sg = idx & 7; }
                const float *pu, *pv; int start, len;
                if (c < TRC)            { pu = g_u0; pv = g_v0; start = c * DCH;        len = min(DCH, NTR - start); }
                else if (c < TRC + TEC) { pu = g_u1; pv = g_v1; start = (c - TRC) * DCH; len = min(DCH, NTE - start); }
                else                    { pu = g_u2; pv = g_v2; start = (c - TRC - TEC) * DCH; len = DCH; }
                if (sg >= 0) { start += sg * 32; len = min(32, len - sg * 32); }
                for (int j = lane; j < len; j += 32) {
                    float x = pu[start + j] * (1.0f / CC2), y = pv[start + j] * (1.0f / CC2);
                    mnx = fminf(mnx, x); mxx = fmaxf(mxx, x);
                    mny = fminf(mny, y); mxy = fmaxf(mxy, y);
                }
            } else {
                int g = it - NCHK * 9;
                int start = g * 32;
                int len = min(32, M - start);
                if (lane < len) {
                    float4 q = g_q[start + lane];
                    mnx = mxx = q.x; mny = mxy = q.y;
                }
            }
            #pragma unroll
            for (int o = 16; o; o >>= 1) {
                mnx = fminf(mnx, __shfl_xor_sync(0xffffffffu, mnx, o));
                mny = fminf(mny, __shfl_xor_sync(0xffffffffu, mny, o));
                mxx = fmaxf(mxx, __shfl_xor_sync(0xffffffffu, mxx, o));
                mxy = fmaxf(mxy, __shfl_xor_sync(0xffffffffu, mxy, o));
            }
            if (lane == 0) {
                float4 bb = make_float4(mnx, mny, mxx, mxy);
                if (it < NCHK) g_cbb[it] = bb;
                else if (it < NCHK * 9) g_sbb[it - NCHK] = bb;
                else g_wbb[it - NCHK * 9] = bb;
            }
        }
    }
}

// ============ k_kde: phase E standalone, grid-stride items ============
__global__ void __launch_bounds__(BLK, 7) k_kde() {
    __shared__ struct {
        ulonglong2 su[DCH/4], sv[DCH/4], sf[DCH/4];
        float4 sbb[8];
    } kd;
    const int tid = threadIdx.x;
    const int M = g_M;
    const int tiles = (M + QT - 1) / QT;
    const int ngroups = (M + 31) >> 5;
    const int nitems = tiles * NCHK;

    for (int item = blockIdx.x; item < nitems; item += gridDim.x) {
        int tile = item / NCHK;
        int c = item - tile * NCHK;

        float4 cb = __ldg(&g_cbb[c]);
        int grp = (tile << 2) + (tid >> 5);
        float4 wb = make_float4(0.f, 0.f, 0.f, 0.f);
        int pass_w = 0;
        if (grp < ngroups) {
            wb = __ldg(&g_wbb[grp]);
            float ddx = fmaxf(0.f, fmaxf(cb.x - wb.z, wb.x - cb.z));
            float ddy = fmaxf(0.f, fmaxf(cb.y - wb.w, wb.y - cb.w));
            pass_w = (ddx * ddx + ddy * ddy) <= CUT2;
        }
        if (__syncthreads_or(pass_w) == 0) continue;   // block-uniform skip

        const float *pu, *pv, *pf; float* dst; int start;
        if (c < TRC)            { pu = g_u0; pv = g_v0; pf = g_f0; dst = g_s0; start = c * DCH; }
        else if (c < TRC + TEC) { pu = g_u1; pv = g_v1; pf = g_f1; dst = g_s1; start = (c - TRC) * DCH; }
        else                    { pu = g_u2; pv = g_v2; pf = g_f2; dst = g_s2; start = (c - TRC - TEC) * DCH; }

        __syncthreads();                 // prior readers of smem
        for (int k = tid; k < 192; k += BLK) {
            int a = k >> 6, kk = k & 63;
            const float* base = (a == 0) ? pu : (a == 1) ? pv : pf;
            const ulonglong2* s = reinterpret_cast<const ulonglong2*>(base + start);
            ulonglong2* d = (a == 0) ? kd.su : (a == 1) ? kd.sv : kd.sf;
            d[kk] = s[kk];
        }
        if (tid < 8) kd.sbb[tid] = g_sbb[(c << 3) + tid];
        __syncthreads();

        if (pass_w) {
            int p = (tile << 7) + tid;
            float4 q = __ldg(&g_q[p < M ? p : 0]);
            unsigned long long qx2 = pk2(q.x, q.x);
            unsigned long long qy2 = pk2(q.y, q.y);
            unsigned long long e2  = pk2(q.z, q.z);
            float ssum = 0.f;
            #pragma unroll 1
            for (int sg = 0; sg < 8; sg++) {
                float4 sb = kd.sbb[sg];
                float gx = fmaxf(0.f, fmaxf(sb.x - wb.z, wb.x - sb.z));
                float gy = fmaxf(0.f, fmaxf(sb.y - wb.w, wb.y - sb.w));
                if (gx * gx + gy * gy > CUT2) continue;   // warp-uniform skip
                int base = sg << 3;
                __half2 h0 = __floats2half2_rn(0.f, 0.f);
                __half2 h1 = h0, h2 = h0, h3 = h0;
                #pragma unroll
                for (int j = 0; j < 8; j += 2) {
                    ulonglong2 U0 = kd.su[base + j],     V0 = kd.sv[base + j],     F0 = kd.sf[base + j];
                    ulonglong2 U1 = kd.su[base + j + 1], V1 = kd.sv[base + j + 1], F1 = kd.sf[base + j + 1];
                    h0 = __hadd2(h0, eunit(U0.x, V0.x, F0.x, qx2, qy2, e2));
                    h1 = __hadd2(h1, eunit(U0.y, V0.y, F0.y, qx2, qy2, e2));
                    h2 = __hadd2(h2, eunit(U1.x, V1.x, F1.x, qx2, qy2, e2));
                    h3 = __hadd2(h3, eunit(U1.y, V1.y, F1.y, qx2, qy2, e2));
                }
                float2 f0 = __half22float2(__hadd2(__hadd2(h0, h1), __hadd2(h2, h3)));
                ssum += f0.x + f0.y;
            }
            if (p < M && ssum != 0.f) atomicAdd(&dst[p], ssum);
        }
    }
}

// ============ k_final: phase F ============
__global__ void k_final() {
    __shared__ double bins[NBINS];
    const int tid = threadIdx.x;
    const int M = g_M;
    for (int s = tid; s < NBINS; s += blockDim.x) bins[s] = 0.0;
    __syncthreads();
    float cntf = (float)g_cnt;
    float p_y = cntf / (float)NB;
    for (int p = blockIdx.x * blockDim.x + tid; p < M; p += gridDim.x * blockDim.x) {
        int bin = __float_as_int(g_q[p].w);
        float ktr = g_s0[p] * (float)(1.0 / (NTR * KDE_NORM_D));
        float kte = g_s1[p] * (float)(1.0 / (NTE * KDE_NORM_D));
        float kw  = g_s2[p] / (fmaxf(cntf, 1.0f) * (float)KDE_NORM_D);
        float p_hs = fminf(fmaxf(kw * p_y / (ktr + 1e-8f), 0.0f), 1.0f);
        float ter = (float)g_hte[bin] * (1.0f / NTE);
        float trr = (float)g_htr[bin] * (1.0f / NTR);
        float d_t = (ter > 0.f) ? kte / ter : 0.f;
        float d_s = (trr > 0.f) ? ktr / trr : 0.f;
        atomicAdd(&bins[bin], (double)(p_hs * (d_t - d_s)));
    }
    __syncthreads();
    for (int s = tid; s < NBINS; s += blockDim.x) {
        double v = bins[s];
        if (v != 0.0) atomicAdd(&g_integral[s], v);
    }
}

// ============ k_ec: phase G ============
__global__ void k_ec(float* __restrict__ out) {
    double ec = 0.0;
    for (int b = 0; b < NBINS; b++) {
        float ter = (float)g_hte[b] * (1.0f / NTE);
        if (ter > 0.f) {
            double integ = g_integral[b] / (double)NMC * 100.0;   // VOLUME
            ec += (double)ter * fabs(integ);
        }
    }
    out[0] = (float)ec;
}

// ---------------- launch ----------------
extern "C" void kernel_launch(void* const* d_in, const int* in_sizes, int n_in,
                              void* d_out, int out_size) {
    const float *bx = nullptr, *trp = nullptr, *tep = nullptr;
    const float *trx = nullptr, *tex = nullptr, *W = nullptr, *bv = nullptr, *mc = nullptr;
    const int *by = nullptr, *bp = nullptr;
    for (int i = 0; i < n_in; i++) {
        switch (in_sizes[i]) {
            case 2048:   bx = (const float*)d_in[i]; break;
            case 1024:   if (!by) by = (const int*)d_in[i]; else bp = (const int*)d_in[i]; break;
            case 20000:  if (!trp) trp = (const float*)d_in[i]; else tex = (const float*)d_in[i]; break;
            case 10000:  tep = (const float*)d_in[i]; break;
            case 40000:  trx = (const float*)d_in[i]; break;
            case 20:     W = (const float*)d_in[i]; break;
            case 10:     bv = (const float*)d_in[i]; break;
            case 300000: mc = (const float*)d_in[i]; break;
            default: break;
        }
    }
    k_pre<<<GRID, BLK>>>(trx, tex, bx, by, bp, trp, tep, mc, W, bv);
    k_kde<<<KGRID, BLK>>>();
    k_final<<<128, 256>>>();
    k_ec<<<1, 1>>>((float*)d_out);
}

// round 13
// speedup vs baseline: 1.0691x; 1.0529x over previous
#include <cuda_runtime.h>
#include <cuda_fp16.h>
#include <math.h>
#include <float.h>

#define NTR   20000
#define NTE   10000
#define NB    1024
#define NBINS 15
#define NMC   10000
#define NPTS  150000
#define NCLS  10

#define NC1D   16
#define NCELLS 256
#define INVCW  1.6f            // 1/0.625 over [-5,5]

#define GRID  1036             // 148 SMs x 7 blocks (k_pre, all-resident)
#define BLK   128
#define NWARP (BLK / 32)
#define SPAN  (GRID * BLK)
#define KGRID 4096             // k_kde grid (wave-scheduled)
#define FGRID 128              // k_final grid

#define DCH   256              // data points per chunk (padded)
#define TRC   79               // ceil(20000/256)
#define TEC   40               // ceil(10000/256)
#define BAC   4                // 1024/256
#define NCHK  (TRC + TEC + BAC)   // 123
#define NTRP  (TRC * DCH)      // 20224
#define NTEP  (TEC * DCH)      // 10240
#define QT    128              // queries per tile
#define MAXG32 ((NPTS + 31) / 32)
#define CUT2  4.2f             // gap^2 cutoff

#define NSH   (4 * NCELLS + 2 * NBINS + 1)   // 1055

// c = log2(e) / (2*BW^2)
#define CC   8.014972449383130f
#define CC2  16.029944898766260f
#define KDE_NORM_D 0.5654866776461628

// ---------------- static device scratch ----------------
__device__ __align__(16) float g_u0[NTRP], g_v0[NTRP], g_f0[NTRP];
__device__ __align__(16) float g_u1[NTEP], g_v1[NTEP], g_f1[NTEP];
__device__ __align__(16) float g_u2[NB],   g_v2[NB],   g_f2[NB];
__device__ float4 g_tq[NPTS];
__device__ float4 g_q[NPTS];
__device__ float  g_s0[NPTS], g_s1[NPTS], g_s2[NPTS];
__device__ int    g_M, g_cnt;
__device__ int    g_ccnt[4 * NCELLS];
__device__ int    g_cur[4 * NCELLS];
__device__ int    g_htr[NBINS], g_hte[NBINS];
__device__ double g_integral[NBINS];
__device__ float4 g_cbb[NCHK];
__device__ float4 g_sbb[NCHK * 8];
__device__ float4 g_wbb[MAXG32];
__device__ __align__(128) int g_bar_cnt;
__device__ __align__(128) int g_bar_gen;

union ShU {
    int sh[NSH];
    struct { int h[4 * NCELLS]; int hbase[4 * NCELLS]; } sc;
};

__device__ __forceinline__ int mort4(int cx, int cy) {
    int m = (cx & 1) | ((cy & 1) << 1);
    m |= ((cx & 2) << 1) | ((cy & 2) << 2);
    m |= ((cx & 4) << 2) | ((cy & 4) << 3);
    m |= ((cx & 8) << 3) | ((cy & 8) << 4);
    return m;
}
__device__ __forceinline__ int cellof(float x, float y) {
    int cx = (int)((x + 5.0f) * INVCW);
    int cy = (int)((y + 5.0f) * INVCW);
    cx = min(NC1D - 1, max(0, cx));
    cy = min(NC1D - 1, max(0, cy));
    return mort4(cx, cy);
}
__device__ __forceinline__ int binof(float p) {
    int b = (int)ceilf(p * 15.0f) - 1;
    b = min(14, max(0, b));
    if (!(p > (float)b * (1.0f / 15.0f))) b -= 1;
    else if (p > (float)(b + 1) * (1.0f / 15.0f)) b += 1;
    if (b < 0 || b > 14) return -1;
    if (!(p > (float)b * (1.0f / 15.0f)) || !(p <= (float)(b + 1) * (1.0f / 15.0f))) return -1;
    return b;
}
__device__ __forceinline__ unsigned long long pk2(float lo, float hi) {
    unsigned long long r;
    asm("mov.b64 %0, {%1, %2};" : "=l"(r) : "f"(lo), "f"(hi));
    return r;
}
__device__ __forceinline__ __half2 eunit(unsigned long long uu, unsigned long long vv,
                                         unsigned long long ff,
                                         unsigned long long qx2, unsigned long long qy2,
                                         unsigned long long e2) {
    unsigned long long t;
    asm("add.rn.f32x2 %0, %1, %2;"      : "=l"(t) : "l"(ff), "l"(e2));
    asm("fma.rn.f32x2 %0, %1, %2, %3;"  : "=l"(t) : "l"(vv), "l"(qy2), "l"(t));
    asm("fma.rn.f32x2 %0, %1, %2, %3;"  : "=l"(t) : "l"(uu), "l"(qx2), "l"(t));
    float lo, hi;
    asm("mov.b64 {%0, %1}, %2;" : "=f"(lo), "=f"(hi) : "l"(t));
    return h2exp2(__floats2half2_rn(lo, hi));
}

// fence-cumulative grid barrier (k_pre only; all GRID blocks resident)
__device__ __forceinline__ void gridbar() {
    __syncthreads();
    if (threadIdx.x == 0) {
        __threadfence();
        int gen = atomicAdd(&g_bar_gen, 0);
        if (atomicAdd(&g_bar_cnt, 1) == GRID - 1) {
            atomicExch(&g_bar_cnt, 0);
            __threadfence();
            atomicExch(&g_bar_gen, gen + 1);
        } else {
            while (*(volatile int*)&g_bar_gen == gen) { __nanosleep(64); }
        }
        __threadfence();
    }
    __syncthreads();
}

// ============ k_pre: phases 0, A (filter/hist), B (scan), C (scatter), D (bboxes) ============
__global__ void __launch_bounds__(BLK, 7) k_pre(
    const float* __restrict__ trx, const float* __restrict__ tex,
    const float* __restrict__ bx, const int* __restrict__ by,
    const int* __restrict__ bp, const float* __restrict__ trp,
    const float* __restrict__ tep, const float* __restrict__ mc,
    const float* __restrict__ W, const float* __restrict__ bvec)
{
    __shared__ ShU u;
    const int tid = threadIdx.x;
    const int gid = blockIdx.x * BLK + tid;

    // ---------- phase 0 ----------
    if (gid < 4 * NCELLS) g_ccnt[gid] = 0;
    else if (gid < 4 * NCELLS + NBINS)       g_htr[gid - 4 * NCELLS] = 0;
    else if (gid < 4 * NCELLS + 2 * NBINS)   g_hte[gid - 4 * NCELLS - NBINS] = 0;
    else if (gid < 4 * NCELLS + 3 * NBINS)   g_integral[gid - 4 * NCELLS - 2 * NBINS] = 0.0;
    else if (gid == 4 * NCELLS + 3 * NBINS)  { g_M = 0; g_cnt = 0; }
    {
        int k = gid - 2048;
        if (k >= 0 && k < NTRP - NTR) { g_u0[NTR + k] = 0.f; g_v0[NTR + k] = 0.f; g_f0[NTR + k] = -1e30f; }
        int k2 = gid - 4096;
        if (k2 >= 0 && k2 < NTEP - NTE) { g_u1[NTE + k2] = 0.f; g_v1[NTE + k2] = 0.f; g_f1[NTE + k2] = -1e30f; }
    }
    gridbar();

    // ---------- phase A ----------
    for (int s = tid; s < NSH; s += BLK) u.sh[s] = 0;
    __syncthreads();
    for (int i0 = 0; i0 < NPTS; i0 += SPAN) {
        int i = i0 + gid;
        if (i < NTR) {
            atomicAdd(&u.sh[NCELLS + cellof(trx[2 * i], trx[2 * i + 1])], 1);
            int b = binof(trp[i]);
            if (b >= 0) atomicAdd(&u.sh[4 * NCELLS + b], 1);
        }
        if (i < NTE) {
            atomicAdd(&u.sh[2 * NCELLS + cellof(tex[2 * i], tex[2 * i + 1])], 1);
            int b = binof(tep[i]);
            if (b >= 0) atomicAdd(&u.sh[4 * NCELLS + NBINS + b], 1);
        }
        if (i < NB) {
            atomicAdd(&u.sh[3 * NCELLS + cellof(bx[2 * i], bx[2 * i + 1])], 1);
            if (by[i] == bp[i]) atomicAdd(&u.sh[4 * NCELLS + 2 * NBINS], 1);
        }
        bool pass = false;
        float qx = 0.f, qy = 0.f;
        int bin = 0;
        if (i < NPTS) {
            bin = i / NMC;
            qx = mc[2 * i]; qy = mc[2 * i + 1];
            float l[NCLS], lmax = -FLT_MAX;
            #pragma unroll
            for (int c = 0; c < NCLS; c++) {
                float v = fmaf(qx, __ldg(&W[c]), fmaf(qy, __ldg(&W[NCLS + c]), __ldg(&bvec[c])));
                l[c] = v; lmax = fmaxf(lmax, v);
            }
            float s = 0.f;
            #pragma unroll
            for (int c = 0; c < NCLS; c++) s += __expf(l[c] - lmax);
            float hs = 1.0f / s;
            float lo = (float)bin * (1.0f / 15.0f);
            float hi = (float)(bin + 1) * (1.0f / 15.0f);
            pass = (hs >= lo && hs <= hi);
        }
        unsigned mask = __ballot_sync(0xffffffffu, pass);
        if (pass) {
            int lane = tid & 31;
            int leader = __ffs(mask) - 1;
            int rank = __popc(mask & ((1u << lane) - 1));
            int base = 0;
            if (lane == leader) base = atomicAdd(&g_M, __popc(mask));
            base = __shfl_sync(mask, base, leader);
            g_tq[base + rank] = make_float4(qx, qy, 0.f, __int_as_float(bin));
            atomicAdd(&u.sh[cellof(qx, qy)], 1);
        }
    }
    __syncthreads();
    for (int s = tid; s < NSH; s += BLK) {
        int v = u.sh[s];
        if (!v) continue;
        if (s < 4 * NCELLS)                    atomicAdd(&g_ccnt[s], v);
        else if (s < 4 * NCELLS + NBINS)       atomicAdd(&g_htr[s - 4 * NCELLS], v);
        else if (s < 4 * NCELLS + 2 * NBINS)   atomicAdd(&g_hte[s - 4 * NCELLS - NBINS], v);
        else                                   atomicAdd(&g_cnt, v);
    }
    gridbar();

    // ---------- phase B ----------
    if (blockIdx.x == 0 && tid < 128) {
        int a = tid >> 5, lane = tid & 31;
        int base = a * NCELLS + lane * 8;
        int v[8], pre[8], run = 0;
        #pragma unroll
        for (int k = 0; k < 8; k++) { v[k] = g_ccnt[base + k]; pre[k] = run; run += v[k]; }
        int inc = run;
        #pragma unroll
        for (int o = 1; o < 32; o <<= 1) {
            int n = __shfl_up_sync(0xffffffffu, inc, o);
            if (lane >= o) inc += n;
        }
        int excl = inc - run;
        #pragma unroll
        for (int k = 0; k < 8; k++) g_cur[base + k] = excl + pre[k];
    }
    gridbar();

    const int M = g_M;

    // ---------- phase C ----------
    for (int i0 = 0; i0 < NPTS; i0 += SPAN) {
        for (int s = tid; s < 4 * NCELLS; s += BLK) u.sc.h[s] = 0;
        __syncthreads();
        int i = i0 + gid;
        float qx = 0.f, qy = 0.f, qw = 0.f; int qc = -1, qr = 0;
        if (i < M) {
            float4 q = g_tq[i];
            qx = q.x; qy = q.y; qw = q.w;
            qc = cellof(qx, qy);
            qr = atomicAdd(&u.sc.h[qc], 1);
        }
        float tx = 0.f, ty = 0.f; int tc = -1, trk = 0;
        if (i < NTR) {
            tx = trx[2 * i]; ty = trx[2 * i + 1];
            tc = cellof(tx, ty);
            trk = atomicAdd(&u.sc.h[NCELLS + tc], 1);
        }
        float ex = 0.f, ey = 0.f; int ecl = -1, erk = 0;
        if (i < NTE) {
            ex = tex[2 * i]; ey = tex[2 * i + 1];
            ecl = cellof(ex, ey);
            erk = atomicAdd(&u.sc.h[2 * NCELLS + ecl], 1);
        }
        float bxx = 0.f, byy = 0.f; int bcl = -1, brk = 0; bool bok = false;
        if (i < NB) {
            bxx = bx[2 * i]; byy = bx[2 * i + 1];
            bok = (by[i] == bp[i]);
            bcl = cellof(bxx, byy);
            brk = atomicAdd(&u.sc.h[3 * NCELLS + bcl], 1);
        }
        __syncthreads();
        for (int s = tid; s < 4 * NCELLS; s += BLK) {
            int c = u.sc.h[s];
            if (c) u.sc.hbase[s] = atomicAdd(&g_cur[s], c);
        }
        __syncthreads();
        if (qc >= 0) {
            int pos = u.sc.hbase[qc] + qr;
            g_q[pos] = make_float4(qx, qy, -CC * (qx * qx + qy * qy), qw);
            g_s0[pos] = 0.f; g_s1[pos] = 0.f; g_s2[pos] = 0.f;
        }
        if (tc >= 0) {
            int pos = u.sc.hbase[NCELLS + tc] + trk;
            g_u0[pos] = CC2 * tx; g_v0[pos] = CC2 * ty; g_f0[pos] = -CC * (tx * tx + ty * ty);
        }
        if (ecl >= 0) {
            int pos = u.sc.hbase[2 * NCELLS + ecl] + erk;
            g_u1[pos] = CC2 * ex; g_v1[pos] = CC2 * ey; g_f1[pos] = -CC * (ex * ex + ey * ey);
        }
        if (bcl >= 0) {
            int pos = u.sc.hbase[3 * NCELLS + bcl] + brk;
            g_u2[pos] = CC2 * bxx; g_v2[pos] = CC2 * byy;
            g_f2[pos] = bok ? -CC * (bxx * bxx + byy * byy) : -1e30f;
        }
        __syncthreads();
    }
    gridbar();

    // ---------- phase D ----------
    const int ngroups = (M + 31) >> 5;
    {
        int gw = blockIdx.x * NWARP + (tid >> 5);
        int lane = tid & 31;
        int nit = NCHK * 9 + ngroups;
        for (int it = gw; it < nit; it += GRID * NWARP) {
            float mnx = FLT_MAX, mny = FLT_MAX, mxx = -FLT_MAX, mxy = -FLT_MAX;
            if (it < NCHK * 9) {
                int c, sg;
                if (it < NCHK) { c = it; sg = -1; }
                else { int idx = it - NCHK; c = idx >> 3; sg = idx & 7; }
                const float *pu, *pv; int start, len;
                if (c < TRC)            { pu = g_u0; pv = g_v0; start = c * DCH;        len = min(DCH, NTR - start); }
                else if (c < TRC + TEC) { pu = g_u1; pv = g_v1; start = (c - TRC) * DCH; len = min(DCH, NTE - start); }
                else                    { pu = g_u2; pv = g_v2; start = (c - TRC - TEC) * DCH; len = DCH; }
                if (sg >= 0) { start += sg * 32; len = min(32, len - sg * 32); }
                for (int j = lane; j < len; j += 32) {
                    float x = pu[start + j] * (1.0f / CC2), y = pv[start + j] * (1.0f / CC2);
                    mnx = fminf(mnx, x); mxx = fmaxf(mxx, x);
                    mny = fminf(mny, y); mxy = fmaxf(mxy, y);
                }
            } else {
                int g = it - NCHK * 9;
                int start = g * 32;
                int len = min(32, M - start);
                if (lane < len) {
                    float4 q = g_q[start + lane];
                    mnx = mxx = q.x; mny = mxy = q.y;
                }
            }
            #pragma unroll
            for (int o = 16; o; o >>= 1) {
                mnx = fminf(mnx, __shfl_xor_sync(0xffffffffu, mnx, o));
                mny = fminf(mny, __shfl_xor_sync(0xffffffffu, mny, o));
                mxx = fmaxf(mxx, __shfl_xor_sync(0xffffffffu, mxx, o));
                mxy = fmaxf(mxy, __shfl_xor_sync(0xffffffffu, mxy, o));
            }
            if (lane == 0) {
                float4 bb = make_float4(mnx, mny, mxx, mxy);
                if (it < NCHK) g_cbb[it] = bb;
                else if (it < NCHK * 9) g_sbb[it - NCHK] = bb;
                else g_wbb[it - NCHK * 9] = bb;
            }
        }
    }
}

// ============ k_kde: phase E standalone, grid-stride items ============
__global__ void __launch_bounds__(BLK, 7) k_kde() {
    __shared__ struct {
        ulonglong2 su[DCH/4], sv[DCH/4], sf[DCH/4];
        float4 sbb[8];
    } kd;
    const int tid = threadIdx.x;
    const int M = g_M;
    const int tiles = (M + QT - 1) / QT;
    const int ngroups = (M + 31) >> 5;
    const int nitems = tiles * NCHK;

    for (int item = blockIdx.x; item < nitems; item += gridDim.x) {
        int tile = item / NCHK;
        int c = item - tile * NCHK;

        float4 cb = __ldg(&g_cbb[c]);
        int grp = (tile << 2) + (tid >> 5);
        float4 wb = make_float4(0.f, 0.f, 0.f, 0.f);
        int pass_w = 0;
        if (grp < ngroups) {
            wb = __ldg(&g_wbb[grp]);
            float ddx = fmaxf(0.f, fmaxf(cb.x - wb.z, wb.x - cb.z));
            float ddy = fmaxf(0.f, fmaxf(cb.y - wb.w, wb.y - cb.w));
            pass_w = (ddx * ddx + ddy * ddy) <= CUT2;
        }
        if (__syncthreads_or(pass_w) == 0) continue;   // block-uniform skip

        const float *pu, *pv, *pf; float* dst; int start;
        if (c < TRC)            { pu = g_u0; pv = g_v0; pf = g_f0; dst = g_s0; start = c * DCH; }
        else if (c < TRC + TEC) { pu = g_u1; pv = g_v1; pf = g_f1; dst = g_s1; start = (c - TRC) * DCH; }
        else                    { pu = g_u2; pv = g_v2; pf = g_f2; dst = g_s2; start = (c - TRC - TEC) * DCH; }

        __syncthreads();                 // prior readers of smem
        for (int k = tid; k < 192; k += BLK) {
            int a = k >> 6, kk = k & 63;
            const float* base = (a == 0) ? pu : (a == 1) ? pv : pf;
            const ulonglong2* s = reinterpret_cast<const ulonglong2*>(base + start);
            ulonglong2* d = (a == 0) ? kd.su : (a == 1) ? kd.sv : kd.sf;
            d[kk] = s[kk];
        }
        if (tid < 8) kd.sbb[tid] = g_sbb[(c << 3) + tid];
        __syncthreads();

        if (pass_w) {
            int p = (tile << 7) + tid;
            float4 q = __ldg(&g_q[p < M ? p : 0]);
            unsigned long long qx2 = pk2(q.x, q.x);
            unsigned long long qy2 = pk2(q.y, q.y);
            unsigned long long e2  = pk2(q.z, q.z);
            float ssum = 0.f;
            #pragma unroll 1
            for (int sg = 0; sg < 8; sg++) {
                float4 sb = kd.sbb[sg];
                float gx = fmaxf(0.f, fmaxf(sb.x - wb.z, wb.x - sb.z));
                float gy = fmaxf(0.f, fmaxf(sb.y - wb.w, wb.y - sb.w));
                if (gx * gx + gy * gy > CUT2) continue;   // warp-uniform skip
                int base = sg << 3;
                __half2 h0 = __floats2half2_rn(0.f, 0.f);
                __half2 h1 = h0, h2 = h0, h3 = h0;
                #pragma unroll
                for (int j = 0; j < 8; j += 2) {
                    ulonglong2 U0 = kd.su[base + j],     V0 = kd.sv[base + j],     F0 = kd.sf[base + j];
                    ulonglong2 U1 = kd.su[base + j + 1], V1 = kd.sv[base + j + 1], F1 = kd.sf[base + j + 1];
                    h0 = __hadd2(h0, eunit(U0.x, V0.x, F0.x, qx2, qy2, e2));
                    h1 = __hadd2(h1, eunit(U0.y, V0.y, F0.y, qx2, qy2, e2));
                    h2 = __hadd2(h2, eunit(U1.x, V1.x, F1.x, qx2, qy2, e2));
                    h3 = __hadd2(h3, eunit(U1.y, V1.y, F1.y, qx2, qy2, e2));
                }
                float2 f0 = __half22float2(__hadd2(__hadd2(h0, h1), __hadd2(h2, h3)));
                ssum += f0.x + f0.y;
            }
            if (p < M && ssum != 0.f) atomicAdd(&dst[p], ssum);
        }
    }
}

// ============ k_final: phase F ============
__global__ void k_final() {
    __shared__ double bins[NBINS];
    const int tid = threadIdx.x;
    const int M = g_M;
    for (int s = tid; s < NBINS; s += blockDim.x) bins[s] = 0.0;
    __syncthreads();
    float cntf = (float)g_cnt;
    float p_y = cntf / (float)NB;
    for (int p = blockIdx.x * blockDim.x + tid; p < M; p += gridDim.x * blockDim.x) {
        int bin = __float_as_int(g_q[p].w);
        float ktr = g_s0[p] * (float)(1.0 / (NTR * KDE_NORM_D));
        float kte = g_s1[p] * (float)(1.0 / (NTE * KDE_NORM_D));
        float kw  = g_s2[p] / (fmaxf(cntf, 1.0f) * (float)KDE_NORM_D);
        float p_hs = fminf(fmaxf(kw * p_y / (ktr + 1e-8f), 0.0f), 1.0f);
        float ter = (float)g_hte[bin] * (1.0f / NTE);
        float trr = (float)g_htr[bin] * (1.0f / NTR);
        float d_t = (ter > 0.f) ? kte / ter : 0.f;
        float d_s = (trr > 0.f) ? ktr / trr : 0.f;
        atomicAdd(&bins[bin], (double)(p_hs * (d_t - d_s)));
    }
    __syncthreads();
    for (int s = tid; s < NBINS; s += blockDim.x) {
        double v = bins[s];
        if (v != 0.0) atomicAdd(&g_integral[s], v);
    }
}

// ============ k_ec: phase G, warp-parallel (1 round-trip of loads) ============
__global__ void k_ec(float* __restrict__ out) {
    int tid = threadIdx.x;
    double term = 0.0;
    if (tid < NBINS) {
        float ter = (float)g_hte[tid] * (1.0f / NTE);
        if (ter > 0.f) {
            double integ = g_integral[tid] / (double)NMC * 100.0;   // VOLUME
            term = (double)ter * fabs(integ);
        }
    }
    #pragma unroll
    for (int o = 16; o; o >>= 1)
        term += __shfl_xor_sync(0xffffffffu, term, o);
    if (tid == 0) out[0] = (float)term;
}

// ---------------- launch ----------------
extern "C" void kernel_launch(void* const* d_in, const int* in_sizes, int n_in,
                              void* d_out, int out_size) {
    const float *bx = nullptr, *trp = nullptr, *tep = nullptr;
    const float *trx = nullptr, *tex = nullptr, *W = nullptr, *bv = nullptr, *mc = nullptr;
    const int *by = nullptr, *bp = nullptr;
    for (int i = 0; i < n_in; i++) {
        switch (in_sizes[i]) {
            case 2048:   bx = (const float*)d_in[i]; break;
            case 1024:   if (!by) by = (const int*)d_in[i]; else bp = (const int*)d_in[i]; break;
            case 20000:  if (!trp) trp = (const float*)d_in[i]; else tex = (const float*)d_in[i]; break;
            case 10000:  tep = (const float*)d_in[i]; break;
            case 40000:  trx = (const float*)d_in[i]; break;
            case 20:     W = (const float*)d_in[i]; break;
            case 10:     bv = (const float*)d_in[i]; break;
            case 300000: mc = (const float*)d_in[i]; break;
            default: break;
        }
    }
    k_pre<<<GRID, BLK>>>(trx, tex, bx, by, bp, trp, tep, mc, W, bv);
    k_kde<<<KGRID, BLK>>>();
    k_final<<<FGRID, 256>>>();
    k_ec<<<1, 32>>>((float*)d_out);
}

// round 14
// speedup vs baseline: 1.2454x; 1.1648x over previous
#include <cuda_runtime.h>
#include <cuda_fp16.h>
#include <math.h>
#include <float.h>

#define NTR   20000
#define NTE   10000
#define NB    1024
#define NBINS 15
#define NMC   10000
#define NPTS  150000
#define NCLS  10

#define NC1D   16
#define NCELLS 256
#define INVCW  1.6f            // 1/0.625 over [-5,5]

#define GRID  1036             // 148 SMs x 7 blocks (k_pre, all-resident)
#define BLK   128
#define NWARP (BLK / 32)
#define SPAN  (GRID * BLK)
#define KGRID 4096             // k_kde grid (wave-scheduled)

#define DCH   256              // data points per chunk (padded)
#define TRC   79               // ceil(20000/256)
#define TEC   40               // ceil(10000/256)
#define BAC   4                // 1024/256
#define NCHK  (TRC + TEC + BAC)   // 123
#define NTRP  (TRC * DCH)      // 20224
#define NTEP  (TEC * DCH)      // 10240
#define QT    128              // queries per tile
#define MAXG32 ((NPTS + 31) / 32)
#define CUT2  3.0f             // gap^2 cutoff == fp16 exp2 underflow boundary

#define NSH   (4 * NCELLS + 2 * NBINS + 1)   // 1055

// c = log2(e) / (2*BW^2)
#define CC   8.014972449383130f
#define CC2  16.029944898766260f
#define KDE_NORM_D 0.5654866776461628

// ---------------- static device scratch ----------------
__device__ __align__(16) float g_u0[NTRP], g_v0[NTRP], g_f0[NTRP];
__device__ __align__(16) float g_u1[NTEP], g_v1[NTEP], g_f1[NTEP];
__device__ __align__(16) float g_u2[NB],   g_v2[NB],   g_f2[NB];
__device__ float4 g_tq[NPTS];
__device__ float4 g_q[NPTS];
__device__ float  g_s0[NPTS], g_s1[NPTS], g_s2[NPTS];
__device__ int    g_M, g_cnt;
__device__ int    g_ccnt[4 * NCELLS];
__device__ int    g_cur[4 * NCELLS];
__device__ int    g_htr[NBINS], g_hte[NBINS];
__device__ double g_integral[NBINS];
__device__ float4 g_cbb[NCHK];
__device__ float4 g_sbb[NCHK * 8];
__device__ float4 g_wbb[MAXG32];
__device__ __align__(128) int g_bar_cnt;
__device__ __align__(128) int g_bar_gen;

union ShU {
    int sh[NSH];
    struct { int h[4 * NCELLS]; int hbase[4 * NCELLS]; } sc;
};

__device__ __forceinline__ int mort4(int cx, int cy) {
    int m = (cx & 1) | ((cy & 1) << 1);
    m |= ((cx & 2) << 1) | ((cy & 2) << 2);
    m |= ((cx & 4) << 2) | ((cy & 4) << 3);
    m |= ((cx & 8) << 3) | ((cy & 8) << 4);
    return m;
}
__device__ __forceinline__ int cellof(float x, float y) {
    int cx = (int)((x + 5.0f) * INVCW);
    int cy = (int)((y + 5.0f) * INVCW);
    cx = min(NC1D - 1, max(0, cx));
    cy = min(NC1D - 1, max(0, cy));
    return mort4(cx, cy);
}
__device__ __forceinline__ int binof(float p) {
    int b = (int)ceilf(p * 15.0f) - 1;
    b = min(14, max(0, b));
    if (!(p > (float)b * (1.0f / 15.0f))) b -= 1;
    else if (p > (float)(b + 1) * (1.0f / 15.0f)) b += 1;
    if (b < 0 || b > 14) return -1;
    if (!(p > (float)b * (1.0f / 15.0f)) || !(p <= (float)(b + 1) * (1.0f / 15.0f))) return -1;
    return b;
}
__device__ __forceinline__ unsigned long long pk2(float lo, float hi) {
    unsigned long long r;
    asm("mov.b64 %0, {%1, %2};" : "=l"(r) : "f"(lo), "f"(hi));
    return r;
}
__device__ __forceinline__ __half2 eunit(unsigned long long uu, unsigned long long vv,
                                         unsigned long long ff,
                                         unsigned long long qx2, unsigned long long qy2,
                                         unsigned long long e2) {
    unsigned long long t;
    asm("add.rn.f32x2 %0, %1, %2;"      : "=l"(t) : "l"(ff), "l"(e2));
    asm("fma.rn.f32x2 %0, %1, %2, %3;"  : "=l"(t) : "l"(vv), "l"(qy2), "l"(t));
    asm("fma.rn.f32x2 %0, %1, %2, %3;"  : "=l"(t) : "l"(uu), "l"(qx2), "l"(t));
    float lo, hi;
    asm("mov.b64 {%0, %1}, %2;" : "=f"(lo), "=f"(hi) : "l"(t));
    return h2exp2(__floats2half2_rn(lo, hi));
}

// fence-cumulative grid barrier (k_pre only; all GRID blocks resident)
__device__ __forceinline__ void gridbar() {
    __syncthreads();
    if (threadIdx.x == 0) {
        __threadfence();
        int gen = atomicAdd(&g_bar_gen, 0);
        if (atomicAdd(&g_bar_cnt, 1) == GRID - 1) {
            atomicExch(&g_bar_cnt, 0);
            __threadfence();
            atomicExch(&g_bar_gen, gen + 1);
        } else {
            while (*(volatile int*)&g_bar_gen == gen) { __nanosleep(64); }
        }
        __threadfence();
    }
    __syncthreads();
}

// ============ k_pre: phases 0, A (filter/hist), B (scan), C (scatter), D (bboxes) ============
__global__ void __launch_bounds__(BLK, 7) k_pre(
    const float* __restrict__ trx, const float* __restrict__ tex,
    const float* __restrict__ bx, const int* __restrict__ by,
    const int* __restrict__ bp, const float* __restrict__ trp,
    const float* __restrict__ tep, const float* __restrict__ mc,
    const float* __restrict__ W, const float* __restrict__ bvec)
{
    __shared__ ShU u;
    const int tid = threadIdx.x;
    const int gid = blockIdx.x * BLK + tid;

    // ---------- phase 0 ----------
    if (gid < 4 * NCELLS) g_ccnt[gid] = 0;
    else if (gid < 4 * NCELLS + NBINS)       g_htr[gid - 4 * NCELLS] = 0;
    else if (gid < 4 * NCELLS + 2 * NBINS)   g_hte[gid - 4 * NCELLS - NBINS] = 0;
    else if (gid < 4 * NCELLS + 3 * NBINS)   g_integral[gid - 4 * NCELLS - 2 * NBINS] = 0.0;
    else if (gid == 4 * NCELLS + 3 * NBINS)  { g_M = 0; g_cnt = 0; }
    {
        int k = gid - 2048;
        if (k >= 0 && k < NTRP - NTR) { g_u0[NTR + k] = 0.f; g_v0[NTR + k] = 0.f; g_f0[NTR + k] = -1e30f; }
        int k2 = gid - 4096;
        if (k2 >= 0 && k2 < NTEP - NTE) { g_u1[NTE + k2] = 0.f; g_v1[NTE + k2] = 0.f; g_f1[NTE + k2] = -1e30f; }
    }
    gridbar();

    // ---------- phase A ----------
    for (int s = tid; s < NSH; s += BLK) u.sh[s] = 0;
    __syncthreads();
    for (int i0 = 0; i0 < NPTS; i0 += SPAN) {
        int i = i0 + gid;
        if (i < NTR) {
            atomicAdd(&u.sh[NCELLS + cellof(trx[2 * i], trx[2 * i + 1])], 1);
            int b = binof(trp[i]);
            if (b >= 0) atomicAdd(&u.sh[4 * NCELLS + b], 1);
        }
        if (i < NTE) {
            atomicAdd(&u.sh[2 * NCELLS + cellof(tex[2 * i], tex[2 * i + 1])], 1);
            int b = binof(tep[i]);
            if (b >= 0) atomicAdd(&u.sh[4 * NCELLS + NBINS + b], 1);
        }
        if (i < NB) {
            atomicAdd(&u.sh[3 * NCELLS + cellof(bx[2 * i], bx[2 * i + 1])], 1);
            if (by[i] == bp[i]) atomicAdd(&u.sh[4 * NCELLS + 2 * NBINS], 1);
        }
        bool pass = false;
        float qx = 0.f, qy = 0.f;
        int bin = 0;
        if (i < NPTS) {
            bin = i / NMC;
            qx = mc[2 * i]; qy = mc[2 * i + 1];
            float l[NCLS], lmax = -FLT_MAX;
            #pragma unroll
            for (int c = 0; c < NCLS; c++) {
                float v = fmaf(qx, __ldg(&W[c]), fmaf(qy, __ldg(&W[NCLS + c]), __ldg(&bvec[c])));
                l[c] = v; lmax = fmaxf(lmax, v);
            }
            float s = 0.f;
            #pragma unroll
            for (int c = 0; c < NCLS; c++) s += __expf(l[c] - lmax);
            float hs = 1.0f / s;
            float lo = (float)bin * (1.0f / 15.0f);
            float hi = (float)(bin + 1) * (1.0f / 15.0f);
            pass = (hs >= lo && hs <= hi);
        }
        unsigned mask = __ballot_sync(0xffffffffu, pass);
        if (pass) {
            int lane = tid & 31;
            int leader = __ffs(mask) - 1;
            int rank = __popc(mask & ((1u << lane) - 1));
            int base = 0;
            if (lane == leader) base = atomicAdd(&g_M, __popc(mask));
            base = __shfl_sync(mask, base, leader);
            g_tq[base + rank] = make_float4(qx, qy, 0.f, __int_as_float(bin));
            atomicAdd(&u.sh[cellof(qx, qy)], 1);
        }
    }
    __syncthreads();
    for (int s = tid; s < NSH; s += BLK) {
        int v = u.sh[s];
        if (!v) continue;
        if (s < 4 * NCELLS)                    atomicAdd(&g_ccnt[s], v);
        else if (s < 4 * NCELLS + NBINS)       atomicAdd(&g_htr[s - 4 * NCELLS], v);
        else if (s < 4 * NCELLS + 2 * NBINS)   atomicAdd(&g_hte[s - 4 * NCELLS - NBINS], v);
        else                                   atomicAdd(&g_cnt, v);
    }
    gridbar();

    // ---------- phase B ----------
    if (blockIdx.x == 0 && tid < 128) {
        int a = tid >> 5, lane = tid & 31;
        int base = a * NCELLS + lane * 8;
        int v[8], pre[8], run = 0;
        #pragma unroll
        for (int k = 0; k < 8; k++) { v[k] = g_ccnt[base + k]; pre[k] = run; run += v[k]; }
        int inc = run;
        #pragma unroll
        for (int o = 1; o < 32; o <<= 1) {
            int n = __shfl_up_sync(0xffffffffu, inc, o);
            if (lane >= o) inc += n;
        }
        int excl = inc - run;
        #pragma unroll
        for (int k = 0; k < 8; k++) g_cur[base + k] = excl + pre[k];
    }
    gridbar();

    const int M = g_M;

    // ---------- phase C ----------
    for (int i0 = 0; i0 < NPTS; i0 += SPAN) {
        for (int s = tid; s < 4 * NCELLS; s += BLK) u.sc.h[s] = 0;
        __syncthreads();
        int i = i0 + gid;
        float qx = 0.f, qy = 0.f, qw = 0.f; int qc = -1, qr = 0;
        if (i < M) {
            float4 q = g_tq[i];
            qx = q.x; qy = q.y; qw = q.w;
            qc = cellof(qx, qy);
            qr = atomicAdd(&u.sc.h[qc], 1);
        }
        float tx = 0.f, ty = 0.f; int tc = -1, trk = 0;
        if (i < NTR) {
            tx = trx[2 * i]; ty = trx[2 * i + 1];
            tc = cellof(tx, ty);
            trk = atomicAdd(&u.sc.h[NCELLS + tc], 1);
        }
        float ex = 0.f, ey = 0.f; int ecl = -1, erk = 0;
        if (i < NTE) {
            ex = tex[2 * i]; ey = tex[2 * i + 1];
            ecl = cellof(ex, ey);
            erk = atomicAdd(&u.sc.h[2 * NCELLS + ecl], 1);
        }
        float bxx = 0.f, byy = 0.f; int bcl = -1, brk = 0; bool bok = false;
        if (i < NB) {
            bxx = bx[2 * i]; byy = bx[2 * i + 1];
            bok = (by[i] == bp[i]);
            bcl = cellof(bxx, byy);
            brk = atomicAdd(&u.sc.h[3 * NCELLS + bcl], 1);
        }
        __syncthreads();
        for (int s = tid; s < 4 * NCELLS; s += BLK) {
            int c = u.sc.h[s];
            if (c) u.sc.hbase[s] = atomicAdd(&g_cur[s], c);
        }
        __syncthreads();
        if (qc >= 0) {
            int pos = u.sc.hbase[qc] + qr;
            g_q[pos] = make_float4(qx, qy, -CC * (qx * qx + qy * qy), qw);
            g_s0[pos] = 0.f; g_s1[pos] = 0.f; g_s2[pos] = 0.f;
        }
        if (tc >= 0) {
            int pos = u.sc.hbase[NCELLS + tc] + trk;
            g_u0[pos] = CC2 * tx; g_v0[pos] = CC2 * ty; g_f0[pos] = -CC * (tx * tx + ty * ty);
        }
        if (ecl >= 0) {
            int pos = u.sc.hbase[2 * NCELLS + ecl] + erk;
            g_u1[pos] = CC2 * ex; g_v1[pos] = CC2 * ey; g_f1[pos] = -CC * (ex * ex + ey * ey);
        }
        if (bcl >= 0) {
            int pos = u.sc.hbase[3 * NCELLS + bcl] + brk;
            g_u2[pos] = CC2 * bxx; g_v2[pos] = CC2 * byy;
            g_f2[pos] = bok ? -CC * (bxx * bxx + byy * byy) : -1e30f;
        }
        __syncthreads();
    }
    gridbar();

    // ---------- phase D ----------
    const int ngroups = (M + 31) >> 5;
    {
        int gw = blockIdx.x * NWARP + (tid >> 5);
        int lane = tid & 31;
        int nit = NCHK * 9 + ngroups;
        for (int it = gw; it < nit; it += GRID * NWARP) {
            float mnx = FLT_MAX, mny = FLT_MAX, mxx = -FLT_MAX, mxy = -FLT_MAX;
            if (it < NCHK * 9) {
                int c, sg;
                if (it < NCHK) { c = it; sg = -1; }
                else { int idx = it - NCHK; c = idx >> 3; sg = idx & 7; }
                const float *pu, *pv; int start, len;
                if (c < TRC)            { pu = g_u0; pv = g_v0; start = c * DCH;        len = min(DCH, NTR - start); }
                else if (c < TRC + TEC) { pu = g_u1; pv = g_v1; start = (c - TRC) * DCH; len = min(DCH, NTE - start); }
                else                    { pu = g_u2; pv = g_v2; start = (c - TRC - TEC) * DCH; len = DCH; }
                if (sg >= 0) { start += sg * 32; len = min(32, len - sg * 32); }
                for (int j = lane; j < len; j += 32) {
                    float x = pu[start + j] * (1.0f / CC2), y = pv[start + j] * (1.0f / CC2);
                    mnx = fminf(mnx, x); mxx = fmaxf(mxx, x);
                    mny = fminf(mny, y); mxy = fmaxf(mxy, y);
                }
            } else {
                int g = it - NCHK * 9;
                int start = g * 32;
                int len = min(32, M - start);
                if (lane < len) {
                    float4 q = g_q[start + lane];
                    mnx = mxx = q.x; mny = mxy = q.y;
                }
            }
            #pragma unroll
            for (int o = 16; o; o >>= 1) {
                mnx = fminf(mnx, __shfl_xor_sync(0xffffffffu, mnx, o));
                mny = fminf(mny, __shfl_xor_sync(0xffffffffu, mny, o));
                mxx = fmaxf(mxx, __shfl_xor_sync(0xffffffffu, mxx, o));
                mxy = fmaxf(mxy, __shfl_xor_sync(0xffffffffu, mxy, o));
            }
            if (lane == 0) {
                float4 bb = make_float4(mnx, mny, mxx, mxy);
                if (it < NCHK) g_cbb[it] = bb;
                else if (it < NCHK * 9) g_sbb[it - NCHK] = bb;
                else g_wbb[it - NCHK * 9] = bb;
            }
        }
    }
}

// ============ k_kde: phase E standalone, grid-stride items ============
__global__ void __launch_bounds__(BLK, 7) k_kde() {
    __shared__ struct {
        ulonglong2 su[DCH/4], sv[DCH/4], sf[DCH/4];
        float4 sbb[8];
    } kd;
    const int tid = threadIdx.x;
    const int M = g_M;
    const int tiles = (M + QT - 1) / QT;
    const int ngroups = (M + 31) >> 5;
    const int nitems = tiles * NCHK;

    for (int item = blockIdx.x; item < nitems; item += gridDim.x) {
        int tile = item / NCHK;
        int c = item - tile * NCHK;

        float4 cb = __ldg(&g_cbb[c]);
        int grp = (tile << 2) + (tid >> 5);
        float4 wb = make_float4(0.f, 0.f, 0.f, 0.f);
        int pass_w = 0;
        if (grp < ngroups) {
            wb = __ldg(&g_wbb[grp]);
            float ddx = fmaxf(0.f, fmaxf(cb.x - wb.z, wb.x - cb.z));
            float ddy = fmaxf(0.f, fmaxf(cb.y - wb.w, wb.y - cb.w));
            pass_w = (ddx * ddx + ddy * ddy) <= CUT2;
        }
        if (__syncthreads_or(pass_w) == 0) continue;   // block-uniform skip

        const float *pu, *pv, *pf; float* dst; int start;
        if (c < TRC)            { pu = g_u0; pv = g_v0; pf = g_f0; dst = g_s0; start = c * DCH; }
        else if (c < TRC + TEC) { pu = g_u1; pv = g_v1; pf = g_f1; dst = g_s1; start = (c - TRC) * DCH; }
        else                    { pu = g_u2; pv = g_v2; pf = g_f2; dst = g_s2; start = (c - TRC - TEC) * DCH; }

        __syncthreads();                 // prior readers of smem
        for (int k = tid; k < 192; k += BLK) {
            int a = k >> 6, kk = k & 63;
            const float* base = (a == 0) ? pu : (a == 1) ? pv : pf;
            const ulonglong2* s = reinterpret_cast<const ulonglong2*>(base + start);
            ulonglong2* d = (a == 0) ? kd.su : (a == 1) ? kd.sv : kd.sf;
            d[kk] = s[kk];
        }
        if (tid < 8) kd.sbb[tid] = g_sbb[(c << 3) + tid];
        __syncthreads();

        if (pass_w) {
            int p = (tile << 7) + tid;
            float4 q = __ldg(&g_q[p < M ? p : 0]);
            unsigned long long qx2 = pk2(q.x, q.x);
            unsigned long long qy2 = pk2(q.y, q.y);
            unsigned long long e2  = pk2(q.z, q.z);
            float ssum = 0.f;
            #pragma unroll 1
            for (int sg = 0; sg < 8; sg++) {
                float4 sb = kd.sbb[sg];
                float gx = fmaxf(0.f, fmaxf(sb.x - wb.z, wb.x - sb.z));
                float gy = fmaxf(0.f, fmaxf(sb.y - wb.w, wb.y - sb.w));
                if (gx * gx + gy * gy > CUT2) continue;   // warp-uniform skip
                int base = sg << 3;
                __half2 h0 = __floats2half2_rn(0.f, 0.f);
                __half2 h1 = h0, h2 = h0, h3 = h0;
                #pragma unroll
                for (int j = 0; j < 8; j += 2) {
                    ulonglong2 U0 = kd.su[base + j],     V0 = kd.sv[base + j],     F0 = kd.sf[base + j];
                    ulonglong2 U1 = kd.su[base + j + 1], V1 = kd.sv[base + j + 1], F1 = kd.sf[base + j + 1];
                    h0 = __hadd2(h0, eunit(U0.x, V0.x, F0.x, qx2, qy2, e2));
                    h1 = __hadd2(h1, eunit(U0.y, V0.y, F0.y, qx2, qy2, e2));
                    h2 = __hadd2(h2, eunit(U1.x, V1.x, F1.x, qx2, qy2, e2));
                    h3 = __hadd2(h3, eunit(U1.y, V1.y, F1.y, qx2, qy2, e2));
                }
                float2 f0 = __half22float2(__hadd2(__hadd2(h0, h1), __hadd2(h2, h3)));
                ssum += f0.x + f0.y;
            }
            if (p < M && ssum != 0.f) atomicAdd(&dst[p], ssum);
        }
    }
}

// ============ k_fin: phases F + G in one single-block kernel ============
__global__ void __launch_bounds__(1024, 1) k_fin(float* __restrict__ out) {
    __shared__ double sb[32 * NBINS];
    __shared__ float ster[NBINS], strr[NBINS];
    const int tid = threadIdx.x;
    const int M = g_M;
    if (tid < NBINS) {
        ster[tid] = (float)g_hte[tid] * (1.0f / NTE);
        strr[tid] = (float)g_htr[tid] * (1.0f / NTR);
    }
    __syncthreads();
    const float cntf = (float)g_cnt;
    const float p_y = cntf / (float)NB;

    float acc[NBINS];
    #pragma unroll
    for (int b = 0; b < NBINS; b++) acc[b] = 0.f;

    for (int p = tid; p < M; p += 1024) {
        float4 q = g_q[p];
        int bin = __float_as_int(q.w);
        float ktr = g_s0[p] * (float)(1.0 / (NTR * KDE_NORM_D));
        float kte = g_s1[p] * (float)(1.0 / (NTE * KDE_NORM_D));
        float kw  = g_s2[p] / (fmaxf(cntf, 1.0f) * (float)KDE_NORM_D);
        float p_hs = fminf(fmaxf(kw * p_y / (ktr + 1e-8f), 0.0f), 1.0f);
        float ter = ster[bin], trr = strr[bin];
        float d_t = (ter > 0.f) ? kte / ter : 0.f;
        float d_s = (trr > 0.f) ? ktr / trr : 0.f;
        float val = p_hs * (d_t - d_s);
        #pragma unroll
        for (int b = 0; b < NBINS; b++) acc[b] += (b == bin) ? val : 0.f;
    }
    // warp reduce each bin
    #pragma unroll
    for (int b = 0; b < NBINS; b++) {
        #pragma unroll
        for (int o = 16; o; o >>= 1)
            acc[b] += __shfl_xor_sync(0xffffffffu, acc[b], o);
    }
    int wid = tid >> 5, lane = tid & 31;
    if (lane == 0) {
        #pragma unroll
        for (int b = 0; b < NBINS; b++) sb[wid * NBINS + b] = (double)acc[b];
    }
    __syncthreads();
    if (tid < 32) {
        double integ = 0.0;
        if (tid < NBINS) {
            for (int w = 0; w < 32; w++) integ += sb[w * NBINS + tid];
        }
        double term = 0.0;
        if (tid < NBINS) {
            float ter = ster[tid];
            if (ter > 0.f)
                term = (double)ter * fabs(integ / (double)NMC * 100.0);   // VOLUME
        }
        #pragma unroll
        for (int o = 16; o; o >>= 1)
            term += __shfl_xor_sync(0xffffffffu, term, o);
        if (tid == 0) out[0] = (float)term;
    }
}

// ---------------- launch ----------------
extern "C" void kernel_launch(void* const* d_in, const int* in_sizes, int n_in,
                              void* d_out, int out_size) {
    const float *bx = nullptr, *trp = nullptr, *tep = nullptr;
    const float *trx = nullptr, *tex = nullptr, *W = nullptr, *bv = nullptr, *mc = nullptr;
    const int *by = nullptr, *bp = nullptr;
    for (int i = 0; i < n_in; i++) {
        switch (in_sizes[i]) {
            case 2048:   bx = (const float*)d_in[i]; break;
            case 1024:   if (!by) by = (const int*)d_in[i]; else bp = (const int*)d_in[i]; break;
            case 20000:  if (!trp) trp = (const float*)d_in[i]; else tex = (const float*)d_in[i]; break;
            case 10000:  tep = (const float*)d_in[i]; break;
            case 40000:  trx = (const float*)d_in[i]; break;
            case 20:     W = (const float*)d_in[i]; break;
            case 10:     bv = (const float*)d_in[i]; break;
            case 300000: mc = (const float*)d_in[i]; break;
            default: break;
        }
    }
    k_pre<<<GRID, BLK>>>(trx, tex, bx, by, bp, trp, tep, mc, W, bv);
    k_kde<<<KGRID, BLK>>>();
    k_fin<<<1, 1024>>>((float*)d_out);
}

// round 15
// speedup vs baseline: 1.2512x; 1.0046x over previous
#include <cuda_runtime.h>
#include <cuda_fp16.h>
#include <math.h>
#include <float.h>

#define NTR   20000
#define NTE   10000
#define NB    1024
#define NBINS 15
#define NMC   10000
#define NPTS  150000
#define NCLS  10

#define NC1D   16
#define NCELLS 256
#define INVCW  1.6f            // 1/0.625 over [-5,5]

#define GRID  1036             // 148 SMs x 7 blocks (k_pre, all-resident)
#define BLK   128
#define NWARP (BLK / 32)
#define SPAN  (GRID * BLK)
#define KGRID 4096             // k_kde grid (wave-scheduled)

#define DCH   128              // data points per chunk (padded)
#define TRC   157              // ceil(20000/128)
#define TEC   79               // ceil(10000/128)
#define BAC   8                // 1024/128
#define NCHK  (TRC + TEC + BAC)   // 244
#define NTRP  (TRC * DCH)      // 20096
#define NTEP  (TEC * DCH)      // 10112
#define QT    128              // queries per tile
#define MAXG32 ((NPTS + 31) / 32)
#define CUT2  3.0f             // gap^2 cutoff == fp16 exp2 underflow boundary

#define NSH   (4 * NCELLS + 2 * NBINS + 1)   // 1055

// c = log2(e) / (2*BW^2)
#define CC   8.014972449383130f
#define CC2  16.029944898766260f
#define KDE_NORM_D 0.5654866776461628

// ---------------- static device scratch ----------------
__device__ __align__(16) float g_u0[NTRP], g_v0[NTRP], g_f0[NTRP];
__device__ __align__(16) float g_u1[NTEP], g_v1[NTEP], g_f1[NTEP];
__device__ __align__(16) float g_u2[NB],   g_v2[NB],   g_f2[NB];
__device__ float4 g_tq[NPTS];
__device__ float4 g_q[NPTS];
__device__ float  g_s0[NPTS], g_s1[NPTS], g_s2[NPTS];
__device__ int    g_M, g_cnt;
__device__ int    g_ccnt[4 * NCELLS];
__device__ int    g_cur[4 * NCELLS];
__device__ int    g_htr[NBINS], g_hte[NBINS];
__device__ double g_integral[NBINS];
__device__ float4 g_cbb[NCHK];
__device__ float4 g_sbb[NCHK * 4];
__device__ float4 g_wbb[MAXG32];
__device__ __align__(128) int g_bar_cnt;
__device__ __align__(128) int g_bar_gen;

union ShU {
    int sh[NSH];
    struct { int h[4 * NCELLS]; int hbase[4 * NCELLS]; } sc;
};

__device__ __forceinline__ int mort4(int cx, int cy) {
    int m = (cx & 1) | ((cy & 1) << 1);
    m |= ((cx & 2) << 1) | ((cy & 2) << 2);
    m |= ((cx & 4) << 2) | ((cy & 4) << 3);
    m |= ((cx & 8) << 3) | ((cy & 8) << 4);
    return m;
}
__device__ __forceinline__ int cellof(float x, float y) {
    int cx = (int)((x + 5.0f) * INVCW);
    int cy = (int)((y + 5.0f) * INVCW);
    cx = min(NC1D - 1, max(0, cx));
    cy = min(NC1D - 1, max(0, cy));
    return mort4(cx, cy);
}
__device__ __forceinline__ int binof(float p) {
    int b = (int)ceilf(p * 15.0f) - 1;
    b = min(14, max(0, b));
    if (!(p > (float)b * (1.0f / 15.0f))) b -= 1;
    else if (p > (float)(b + 1) * (1.0f / 15.0f)) b += 1;
    if (b < 0 || b > 14) return -1;
    if (!(p > (float)b * (1.0f / 15.0f)) || !(p <= (float)(b + 1) * (1.0f / 15.0f))) return -1;
    return b;
}
__device__ __forceinline__ unsigned long long pk2(float lo, float hi) {
    unsigned long long r;
    asm("mov.b64 %0, {%1, %2};" : "=l"(r) : "f"(lo), "f"(hi));
    return r;
}
__device__ __forceinline__ __half2 eunit(unsigned long long uu, unsigned long long vv,
                                         unsigned long long ff,
                                         unsigned long long qx2, unsigned long long qy2,
                                         unsigned long long e2) {
    unsigned long long t;
    asm("add.rn.f32x2 %0, %1, %2;"      : "=l"(t) : "l"(ff), "l"(e2));
    asm("fma.rn.f32x2 %0, %1, %2, %3;"  : "=l"(t) : "l"(vv), "l"(qy2), "l"(t));
    asm("fma.rn.f32x2 %0, %1, %2, %3;"  : "=l"(t) : "l"(uu), "l"(qx2), "l"(t));
    float lo, hi;
    asm("mov.b64 {%0, %1}, %2;" : "=f"(lo), "=f"(hi) : "l"(t));
    return h2exp2(__floats2half2_rn(lo, hi));
}

// fence-cumulative grid barrier (k_pre only; all GRID blocks resident)
__device__ __forceinline__ void gridbar() {
    __syncthreads();
    if (threadIdx.x == 0) {
        __threadfence();
        int gen = atomicAdd(&g_bar_gen, 0);
        if (atomicAdd(&g_bar_cnt, 1) == GRID - 1) {
            atomicExch(&g_bar_cnt, 0);
            __threadfence();
            atomicExch(&g_bar_gen, gen + 1);
        } else {
            while (*(volatile int*)&g_bar_gen == gen) { __nanosleep(64); }
        }
        __threadfence();
    }
    __syncthreads();
}

// ============ k_pre: phases 0, A (filter/hist), B (scan), C (scatter), D (bboxes) ============
__global__ void __launch_bounds__(BLK, 7) k_pre(
    const float* __restrict__ trx, const float* __restrict__ tex,
    const float* __restrict__ bx, const int* __restrict__ by,
    const int* __restrict__ bp, const float* __restrict__ trp,
    const float* __restrict__ tep, const float* __restrict__ mc,
    const float* __restrict__ W, const float* __restrict__ bvec)
{
    __shared__ ShU u;
    const int tid = threadIdx.x;
    const int gid = blockIdx.x * BLK + tid;

    // ---------- phase 0 ----------
    if (gid < 4 * NCELLS) g_ccnt[gid] = 0;
    else if (gid < 4 * NCELLS + NBINS)       g_htr[gid - 4 * NCELLS] = 0;
    else if (gid < 4 * NCELLS + 2 * NBINS)   g_hte[gid - 4 * NCELLS - NBINS] = 0;
    else if (gid < 4 * NCELLS + 3 * NBINS)   g_integral[gid - 4 * NCELLS - 2 * NBINS] = 0.0;
    else if (gid == 4 * NCELLS + 3 * NBINS)  { g_M = 0; g_cnt = 0; }
    {
        int k = gid - 2048;
        if (k >= 0 && k < NTRP - NTR) { g_u0[NTR + k] = 0.f; g_v0[NTR + k] = 0.f; g_f0[NTR + k] = -1e30f; }
        int k2 = gid - 4096;
        if (k2 >= 0 && k2 < NTEP - NTE) { g_u1[NTE + k2] = 0.f; g_v1[NTE + k2] = 0.f; g_f1[NTE + k2] = -1e30f; }
    }
    gridbar();

    // ---------- phase A ----------
    for (int s = tid; s < NSH; s += BLK) u.sh[s] = 0;
    __syncthreads();
    for (int i0 = 0; i0 < NPTS; i0 += SPAN) {
        int i = i0 + gid;
        if (i < NTR) {
            atomicAdd(&u.sh[NCELLS + cellof(trx[2 * i], trx[2 * i + 1])], 1);
            int b = binof(trp[i]);
            if (b >= 0) atomicAdd(&u.sh[4 * NCELLS + b], 1);
        }
        if (i < NTE) {
            atomicAdd(&u.sh[2 * NCELLS + cellof(tex[2 * i], tex[2 * i + 1])], 1);
            int b = binof(tep[i]);
            if (b >= 0) atomicAdd(&u.sh[4 * NCELLS + NBINS + b], 1);
        }
        if (i < NB) {
            atomicAdd(&u.sh[3 * NCELLS + cellof(bx[2 * i], bx[2 * i + 1])], 1);
            if (by[i] == bp[i]) atomicAdd(&u.sh[4 * NCELLS + 2 * NBINS], 1);
        }
        bool pass = false;
        float qx = 0.f, qy = 0.f;
        int bin = 0;
        if (i < NPTS) {
            bin = i / NMC;
            qx = mc[2 * i]; qy = mc[2 * i + 1];
            float l[NCLS], lmax = -FLT_MAX;
            #pragma unroll
            for (int c = 0; c < NCLS; c++) {
                float v = fmaf(qx, __ldg(&W[c]), fmaf(qy, __ldg(&W[NCLS + c]), __ldg(&bvec[c])));
                l[c] = v; lmax = fmaxf(lmax, v);
            }
            float s = 0.f;
            #pragma unroll
            for (int c = 0; c < NCLS; c++) s += __expf(l[c] - lmax);
            float hs = 1.0f / s;
            float lo = (float)bin * (1.0f / 15.0f);
            float hi = (float)(bin + 1) * (1.0f / 15.0f);
            pass = (hs >= lo && hs <= hi);
        }
        unsigned mask = __ballot_sync(0xffffffffu, pass);
        if (pass) {
            int lane = tid & 31;
            int leader = __ffs(mask) - 1;
            int rank = __popc(mask & ((1u << lane) - 1));
            int base = 0;
            if (lane == leader) base = atomicAdd(&g_M, __popc(mask));
            base = __shfl_sync(mask, base, leader);
            g_tq[base + rank] = make_float4(qx, qy, 0.f, __int_as_float(bin));
            atomicAdd(&u.sh[cellof(qx, qy)], 1);
        }
    }
    __syncthreads();
    for (int s = tid; s < NSH; s += BLK) {
        int v = u.sh[s];
        if (!v) continue;
        if (s < 4 * NCELLS)                    atomicAdd(&g_ccnt[s], v);
        else if (s < 4 * NCELLS + NBINS)       atomicAdd(&g_htr[s - 4 * NCELLS], v);
        else if (s < 4 * NCELLS + 2 * NBINS)   atomicAdd(&g_hte[s - 4 * NCELLS - NBINS], v);
        else                                   atomicAdd(&g_cnt, v);
    }
    gridbar();

    // ---------- phase B ----------
    if (blockIdx.x == 0 && tid < 128) {
        int a = tid >> 5, lane = tid & 31;
        int base = a * NCELLS + lane * 8;
        int v[8], pre[8], run = 0;
        #pragma unroll
        for (int k = 0; k < 8; k++) { v[k] = g_ccnt[base + k]; pre[k] = run; run += v[k]; }
        int inc = run;
        #pragma unroll
        for (int o = 1; o < 32; o <<= 1) {
            int n = __shfl_up_sync(0xffffffffu, inc, o);
            if (lane >= o) inc += n;
        }
        int excl = inc - run;
        #pragma unroll
        for (int k = 0; k < 8; k++) g_cur[base + k] = excl + pre[k];
    }
    gridbar();

    const int M = g_M;

    // ---------- phase C ----------
    for (int i0 = 0; i0 < NPTS; i0 += SPAN) {
        for (int s = tid; s < 4 * NCELLS; s += BLK) u.sc.h[s] = 0;
        __syncthreads();
        int i = i0 + gid;
        float qx = 0.f, qy = 0.f, qw = 0.f; int qc = -1, qr = 0;
        if (i < M) {
            float4 q = g_tq[i];
            qx = q.x; qy = q.y; qw = q.w;
            qc = cellof(qx, qy);
            qr = atomicAdd(&u.sc.h[qc], 1);
        }
        float tx = 0.f, ty = 0.f; int tc = -1, trk = 0;
        if (i < NTR) {
            tx = trx[2 * i]; ty = trx[2 * i + 1];
            tc = cellof(tx, ty);
            trk = atomicAdd(&u.sc.h[NCELLS + tc], 1);
        }
        float ex = 0.f, ey = 0.f; int ecl = -1, erk = 0;
        if (i < NTE) {
            ex = tex[2 * i]; ey = tex[2 * i + 1];
            ecl = cellof(ex, ey);
            erk = atomicAdd(&u.sc.h[2 * NCELLS + ecl], 1);
        }
        float bxx = 0.f, byy = 0.f; int bcl = -1, brk = 0; bool bok = false;
        if (i < NB) {
            bxx = bx[2 * i]; byy = bx[2 * i + 1];
            bok = (by[i] == bp[i]);
            bcl = cellof(bxx, byy);
            brk = atomicAdd(&u.sc.h[3 * NCELLS + bcl], 1);
        }
        __syncthreads();
        for (int s = tid; s < 4 * NCELLS; s += BLK) {
            int c = u.sc.h[s];
            if (c) u.sc.hbase[s] = atomicAdd(&g_cur[s], c);
        }
        __syncthreads();
        if (qc >= 0) {
            int pos = u.sc.hbase[qc] + qr;
            g_q[pos] = make_float4(qx, qy, -CC * (qx * qx + qy * qy), qw);
            g_s0[pos] = 0.f; g_s1[pos] = 0.f; g_s2[pos] = 0.f;
        }
        if (tc >= 0) {
            int pos = u.sc.hbase[NCELLS + tc] + trk;
            g_u0[pos] = CC2 * tx; g_v0[pos] = CC2 * ty; g_f0[pos] = -CC * (tx * tx + ty * ty);
        }
        if (ecl >= 0) {
            int pos = u.sc.hbase[2 * NCELLS + ecl] + erk;
            g_u1[pos] = CC2 * ex; g_v1[pos] = CC2 * ey; g_f1[pos] = -CC * (ex * ex + ey * ey);
        }
        if (bcl >= 0) {
            int pos = u.sc.hbase[3 * NCELLS + bcl] + brk;
            g_u2[pos] = CC2 * bxx; g_v2[pos] = CC2 * byy;
            g_f2[pos] = bok ? -CC * (bxx * bxx + byy * byy) : -1e30f;
        }
        __syncthreads();
    }
    gridbar();

    // ---------- phase D: chunk bboxes, 32-pt subgroup bboxes (4/chunk), query-group bboxes ----------
    const int ngroups = (M + 31) >> 5;
    {
        int gw = blockIdx.x * NWARP + (tid >> 5);
        int lane = tid & 31;
        int nit = NCHK * 5 + ngroups;
        for (int it = gw; it < nit; it += GRID * NWARP) {
            float mnx = FLT_MAX, mny = FLT_MAX, mxx = -FLT_MAX, mxy = -FLT_MAX;
            if (it < NCHK * 5) {
                int c, sg;
                if (it < NCHK) { c = it; sg = -1; }
                else { int idx = it - NCHK; c = idx >> 2; sg = idx & 3; }
                const float *pu, *pv; int start, len;
                if (c < TRC)            { pu = g_u0; pv = g_v0; start = c * DCH;        len = min(DCH, NTR - start); }
                else if (c < TRC + TEC) { pu = g_u1; pv = g_v1; start = (c - TRC) * DCH; len = min(DCH, NTE - start); }
                else                    { pu = g_u2; pv = g_v2; start = (c - TRC - TEC) * DCH; len = DCH; }
                if (sg >= 0) { start += sg * 32; len = min(32, len - sg * 32); }
                for (int j = lane; j < len; j += 32) {
                    float x = pu[start + j] * (1.0f / CC2), y = pv[start + j] * (1.0f / CC2);
                    mnx = fminf(mnx, x); mxx = fmaxf(mxx, x);
                    mny = fminf(mny, y); mxy = fmaxf(mxy, y);
                }
            } else {
                int g = it - NCHK * 5;
                int start = g * 32;
                int len = min(32, M - start);
                if (lane < len) {
                    float4 q = g_q[start + lane];
                    mnx = mxx = q.x; mny = mxy = q.y;
                }
            }
            #pragma unroll
            for (int o = 16; o; o >>= 1) {
                mnx = fminf(mnx, __shfl_xor_sync(0xffffffffu, mnx, o));
                mny = fminf(mny, __shfl_xor_sync(0xffffffffu, mny, o));
                mxx = fmaxf(mxx, __shfl_xor_sync(0xffffffffu, mxx, o));
                mxy = fmaxf(mxy, __shfl_xor_sync(0xffffffffu, mxy, o));
            }
            if (lane == 0) {
                float4 bb = make_float4(mnx, mny, mxx, mxy);
                if (it < NCHK) g_cbb[it] = bb;
                else if (it < NCHK * 5) g_sbb[it - NCHK] = bb;
                else g_wbb[it - NCHK * 5] = bb;
            }
        }
    }
}

// ============ k_kde: phase E standalone, grid-stride items ============
__global__ void __launch_bounds__(BLK, 7) k_kde() {
    __shared__ struct {
        ulonglong2 su[DCH/4], sv[DCH/4], sf[DCH/4];
        float4 sbb[4];
    } kd;
    const int tid = threadIdx.x;
    const int M = g_M;
    const int tiles = (M + QT - 1) / QT;
    const int ngroups = (M + 31) >> 5;
    const int nitems = tiles * NCHK;

    for (int item = blockIdx.x; item < nitems; item += gridDim.x) {
        int tile = item / NCHK;
        int c = item - tile * NCHK;

        float4 cb = __ldg(&g_cbb[c]);
        int grp = (tile << 2) + (tid >> 5);
        float4 wb = make_float4(0.f, 0.f, 0.f, 0.f);
        int pass_w = 0;
        if (grp < ngroups) {
            wb = __ldg(&g_wbb[grp]);
            float ddx = fmaxf(0.f, fmaxf(cb.x - wb.z, wb.x - cb.z));
            float ddy = fmaxf(0.f, fmaxf(cb.y - wb.w, wb.y - cb.w));
            pass_w = (ddx * ddx + ddy * ddy) <= CUT2;
        }
        if (__syncthreads_or(pass_w) == 0) continue;   // block-uniform skip

        const float *pu, *pv, *pf; float* dst; int start;
        if (c < TRC)            { pu = g_u0; pv = g_v0; pf = g_f0; dst = g_s0; start = c * DCH; }
        else if (c < TRC + TEC) { pu = g_u1; pv = g_v1; pf = g_f1; dst = g_s1; start = (c - TRC) * DCH; }
        else                    { pu = g_u2; pv = g_v2; pf = g_f2; dst = g_s2; start = (c - TRC - TEC) * DCH; }

        __syncthreads();                 // prior readers of smem
        if (tid < 96) {
            int a = tid >> 5, kk = tid & 31;
            const float* base = (a == 0) ? pu : (a == 1) ? pv : pf;
            const ulonglong2* s = reinterpret_cast<const ulonglong2*>(base + start);
            ulonglong2* d = (a == 0) ? kd.su : (a == 1) ? kd.sv : kd.sf;
            d[kk] = s[kk];
        }
        if (tid < 4) kd.sbb[tid] = g_sbb[(c << 2) + tid];
        __syncthreads();

        if (pass_w) {
            int p = (tile << 7) + tid;
            float4 q = __ldg(&g_q[p < M ? p : 0]);
            unsigned long long qx2 = pk2(q.x, q.x);
            unsigned long long qy2 = pk2(q.y, q.y);
            unsigned long long e2  = pk2(q.z, q.z);
            float ssum = 0.f;
            #pragma unroll 1
            for (int sg = 0; sg < 4; sg++) {        // 4 subgroups of 32 points
                float4 sb = kd.sbb[sg];
                float gx = fmaxf(0.f, fmaxf(sb.x - wb.z, wb.x - sb.z));
                float gy = fmaxf(0.f, fmaxf(sb.y - wb.w, wb.y - sb.w));
                if (gx * gx + gy * gy > CUT2) continue;   // warp-uniform skip
                int base = sg << 3;
                __half2 h0 = __floats2half2_rn(0.f, 0.f);
                __half2 h1 = h0, h2 = h0, h3 = h0;
                #pragma unroll
                for (int j = 0; j < 8; j += 2) {
                    ulonglong2 U0 = kd.su[base + j],     V0 = kd.sv[base + j],     F0 = kd.sf[base + j];
                    ulonglong2 U1 = kd.su[base + j + 1], V1 = kd.sv[base + j + 1], F1 = kd.sf[base + j + 1];
                    h0 = __hadd2(h0, eunit(U0.x, V0.x, F0.x, qx2, qy2, e2));
                    h1 = __hadd2(h1, eunit(U0.y, V0.y, F0.y, qx2, qy2, e2));
                    h2 = __hadd2(h2, eunit(U1.x, V1.x, F1.x, qx2, qy2, e2));
                    h3 = __hadd2(h3, eunit(U1.y, V1.y, F1.y, qx2, qy2, e2));
                }
                float2 f0 = __half22float2(__hadd2(__hadd2(h0, h1), __hadd2(h2, h3)));
                ssum += f0.x + f0.y;
            }
            if (p < M && ssum != 0.f) atomicAdd(&dst[p], ssum);
        }
    }
}

// ============ k_fin: phases F + G in one single-block kernel ============
__global__ void __launch_bounds__(1024, 1) k_fin(float* __restrict__ out) {
    __shared__ double sb[32 * NBINS];
    __shared__ float ster[NBINS], strr[NBINS];
    const int tid = threadIdx.x;
    const int M = g_M;
    if (tid < NBINS) {
        ster[tid] = (float)g_hte[tid] * (1.0f / NTE);
        strr[tid] = (float)g_htr[tid] * (1.0f / NTR);
    }
    __syncthreads();
    const float cntf = (float)g_cnt;
    const float p_y = cntf / (float)NB;

    float acc[NBINS];
    #pragma unroll
    for (int b = 0; b < NBINS; b++) acc[b] = 0.f;

    for (int p = tid; p < M; p += 1024) {
        float4 q = g_q[p];
        int bin = __float_as_int(q.w);
        float ktr = g_s0[p] * (float)(1.0 / (NTR * KDE_NORM_D));
        float kte = g_s1[p] * (float)(1.0 / (NTE * KDE_NORM_D));
        float kw  = g_s2[p] / (fmaxf(cntf, 1.0f) * (float)KDE_NORM_D);
        float p_hs = fminf(fmaxf(kw * p_y / (ktr + 1e-8f), 0.0f), 1.0f);
        float ter = ster[bin], trr = strr[bin];
        float d_t = (ter > 0.f) ? kte / ter : 0.f;
        float d_s = (trr > 0.f) ? ktr / trr : 0.f;
        float val = p_hs * (d_t - d_s);
        #pragma unroll
        for (int b = 0; b < NBINS; b++) acc[b] += (b == bin) ? val : 0.f;
    }
    // warp reduce each bin
    #pragma unroll
    for (int b = 0; b < NBINS; b++) {
        #pragma unroll
        for (int o = 16; o; o >>= 1)
            acc[b] += __shfl_xor_sync(0xffffffffu, acc[b], o);
    }
    int wid = tid >> 5, lane = tid & 31;
    if (lane == 0) {
        #pragma unroll
        for (int b = 0; b < NBINS; b++) sb[wid * NBINS + b] = (double)acc[b];
    }
    __syncthreads();
    if (tid < 32) {
        double integ = 0.0;
        if (tid < NBINS) {
            for (int w = 0; w < 32; w++) integ += sb[w * NBINS + tid];
        }
        double term = 0.0;
        if (tid < NBINS) {
            float ter = ster[tid];
            if (ter > 0.f)
                term = (double)ter * fabs(integ / (double)NMC * 100.0);   // VOLUME
        }
        #pragma unroll
        for (int o = 16; o; o >>= 1)
            term += __shfl_xor_sync(0xffffffffu, term, o);
        if (tid == 0) out[0] = (float)term;
    }
}

// ---------------- launch ----------------
extern "C" void kernel_launch(void* const* d_in, const int* in_sizes, int n_in,
                              void* d_out, int out_size) {
    const float *bx = nullptr, *trp = nullptr, *tep = nullptr;
    const float *trx = nullptr, *tex = nullptr, *W = nullptr, *bv = nullptr, *mc = nullptr;
    const int *by = nullptr, *bp = nullptr;
    for (int i = 0; i < n_in; i++) {
        switch (in_sizes[i]) {
            case 2048:   bx = (const float*)d_in[i]; break;
            case 1024:   if (!by) by = (const int*)d_in[i]; else bp = (const int*)d_in[i]; break;
            case 20000:  if (!trp) trp = (const float*)d_in[i]; else tex = (const float*)d_in[i]; break;
            case 10000:  tep = (const float*)d_in[i]; break;
            case 40000:  trx = (const float*)d_in[i]; break;
            case 20:     W = (const float*)d_in[i]; break;
            case 10:     bv = (const float*)d_in[i]; break;
            case 300000: mc = (const float*)d_in[i]; break;
            default: break;
        }
    }
    k_pre<<<GRID, BLK>>>(trx, tex, bx, by, bp, trp, tep, mc, W, bv);
    k_kde<<<KGRID, BLK>>>();
    k_fin<<<1, 1024>>>((float*)d_out);
}